// round 8
// baseline (speedup 1.0000x reference)
#include <cuda_runtime.h>
#include <cuda_bf16.h>
#include <cstdint>
#include <math.h>

// ===========================================================================
// SelfAttention via mma.sync (HMMA bf16, base sm_103 ISA) with 2-term
// error-compensated splits: X = Xh + Xl (bf16); D = Xh*Yh + Xh*Yl + Xl*Yh.
// R7: 64x64 warp tiles (CTA 256x128) to relieve smem-BW bound; merged Q/K
// projection launch; 1/sqrt(D) folded into the scores epilogue.
// ===========================================================================

#define BATCH 8
#define SEQ   2048
#define HID   512
#define MROWS (BATCH * SEQ)   // 16384

// ---------------- scratch (__device__ globals) ----------------
__device__ __nv_bfloat16 g_xh[MROWS * HID];
__device__ __nv_bfloat16 g_xl[MROWS * HID];
__device__ __nv_bfloat16 g_xTh[MROWS * HID];   // per-batch [512,2048]
__device__ __nv_bfloat16 g_xTl[MROWS * HID];
__device__ __nv_bfloat16 g_WTh[2 * HID * HID]; // slot0 = WqT, slot1 = WkT
__device__ __nv_bfloat16 g_WTl[2 * HID * HID];
__device__ __nv_bfloat16 g_QKh[2 * MROWS * HID];  // slot0 = Q, slot1 = K
__device__ __nv_bfloat16 g_QKl[2 * MROWS * HID];
__device__ float         g_S [(size_t)BATCH * SEQ * SEQ];   // 128 MB
__device__ __nv_bfloat16 g_Ph[(size_t)BATCH * SEQ * SEQ];   // 64 MB
__device__ __nv_bfloat16 g_Pl[(size_t)BATCH * SEQ * SEQ];   // 64 MB

// ---------------- asm helpers (base ISA) ----------------
__device__ __forceinline__ void ldsm_x4(uint32_t* r, uint32_t addr) {
    asm volatile("ldmatrix.sync.aligned.m8n8.x4.shared.b16 {%0,%1,%2,%3}, [%4];"
                 : "=r"(r[0]), "=r"(r[1]), "=r"(r[2]), "=r"(r[3]) : "r"(addr));
}
__device__ __forceinline__ void mma_bf16(float* d, const uint32_t* a, const uint32_t* b) {
    asm volatile(
        "mma.sync.aligned.m16n8k16.row.col.f32.bf16.bf16.f32 "
        "{%0,%1,%2,%3}, {%4,%5,%6,%7}, {%8,%9}, {%0,%1,%2,%3};"
        : "+f"(d[0]), "+f"(d[1]), "+f"(d[2]), "+f"(d[3])
        : "r"(a[0]), "r"(a[1]), "r"(a[2]), "r"(a[3]), "r"(b[0]), "r"(b[1]));
}
__device__ __forceinline__ uint32_t smem_to_u32(const void* p) {
    uint32_t a;
    asm("{ .reg .u64 t; cvta.to.shared.u64 t, %1; cvt.u32.u64 %0, t; }"
        : "=r"(a) : "l"(p));
    return a;
}
__device__ __forceinline__ void cp_async16(uint32_t dst, const void* src) {
    asm volatile("cp.async.cg.shared.global [%0], [%1], 16;"
                 :: "r"(dst), "l"(src));
}
__device__ __forceinline__ void cp_commit() {
    asm volatile("cp.async.commit_group;");
}
template <int N>
__device__ __forceinline__ void cp_wait() {
    asm volatile("cp.async.wait_group %0;" :: "n"(N));
}

// ---------------- prep kernels ----------------
__global__ __launch_bounds__(256) void split_planes(
    const float* __restrict__ src, __nv_bfloat16* __restrict__ h,
    __nv_bfloat16* __restrict__ l, int n)
{
    int i = blockIdx.x * 256 + threadIdx.x;
    if (i < n) {
        float v = src[i];
        __nv_bfloat16 hi = __float2bfloat16(v);
        h[i] = hi;
        l[i] = __float2bfloat16(v - __bfloat162float(hi));
    }
}

__global__ __launch_bounds__(256) void transpose_split(
    const float* __restrict__ src, __nv_bfloat16* __restrict__ h,
    __nv_bfloat16* __restrict__ l, int R, int C)
{
    __shared__ float t[32][33];
    size_t base = (size_t)blockIdx.z * R * C;
    int c0 = blockIdx.x * 32, r0 = blockIdx.y * 32;
    int tx = threadIdx.x, ty = threadIdx.y;
#pragma unroll
    for (int j = 0; j < 4; j++)
        t[ty + j * 8][tx] = src[base + (size_t)(r0 + ty + j * 8) * C + c0 + tx];
    __syncthreads();
#pragma unroll
    for (int j = 0; j < 4; j++) {
        float v = t[tx][ty + j * 8];
        __nv_bfloat16 hi = __float2bfloat16(v);
        size_t o = base + (size_t)(c0 + ty + j * 8) * R + r0 + tx;
        h[o] = hi;
        l[o] = __float2bfloat16(v - __bfloat162float(hi));
    }
}

// ---------------- softmax: register-resident, emits bf16 hi/lo planes ------
__global__ __launch_bounds__(256) void softmax_split(
    const float* __restrict__ S, __nv_bfloat16* __restrict__ Ph,
    __nv_bfloat16* __restrict__ Pl)
{
    __shared__ float red[256];
    const int tid = threadIdx.x;
    const size_t row = (size_t)blockIdx.x * SEQ;
    const float* p = S + row;

    float v[8];
#pragma unroll
    for (int j = 0; j < 8; j++) v[j] = p[tid + j * 256];

    float m = v[0];
#pragma unroll
    for (int j = 1; j < 8; j++) m = fmaxf(m, v[j]);
    red[tid] = m;
    __syncthreads();
    for (int s = 128; s > 0; s >>= 1) {
        if (tid < s) red[tid] = fmaxf(red[tid], red[tid + s]);
        __syncthreads();
    }
    m = red[0];
    __syncthreads();

    float sum = 0.f;
#pragma unroll
    for (int j = 0; j < 8; j++) {
        v[j] = __expf(v[j] - m);
        sum += v[j];
    }
    red[tid] = sum;
    __syncthreads();
    for (int s = 128; s > 0; s >>= 1) {
        if (tid < s) red[tid] += red[tid + s];
        __syncthreads();
    }
    float inv = 1.0f / red[0];
#pragma unroll
    for (int j = 0; j < 8; j++) {
        float e = v[j] * inv;
        __nv_bfloat16 hi = __float2bfloat16(e);
        Ph[row + tid + j * 256] = hi;
        Pl[row + tid + j * 256] = __float2bfloat16(e - __bfloat162float(hi));
    }
}

// ===========================================================================
// HMMA GEMM, CTA tile 256x128, warp tile 64x64 (warp grid 4x2), K-chunk 32,
// 2-stage cp.async. C[M,N] = A[M,K]@B[N,K]^T, A/B as (hi,lo) bf16 planes.
// Row stride in smem: 80B (32 halves + 16B pad) — ldsm conflict-free.
// Epilogue: Cf fp32 (*scale)  OR  (acc+bias[z])*scale -> (Ch,Cl) planes.
// ===========================================================================
#define A_PLANE_BYTES (256 * 80)          // 20480
#define B_PLANE_BYTES (128 * 80)          // 10240
#define STAGE_BYTES   (2 * A_PLANE_BYTES + 2 * B_PLANE_BYTES)  // 61440
#define GSMEM_TOTAL   (2 * STAGE_BYTES)   // 122880

__global__ __launch_bounds__(256, 1) void gemm_bf16x2(
    const __nv_bfloat16* __restrict__ Ah, const __nv_bfloat16* __restrict__ Al,
    long long sAb,
    const __nv_bfloat16* __restrict__ Bh, const __nv_bfloat16* __restrict__ Bl,
    long long sBb,
    const float* __restrict__ bias, const float* __restrict__ bias2,
    float scale,
    float* __restrict__ Cf,
    __nv_bfloat16* __restrict__ Ch, __nv_bfloat16* __restrict__ Cl,
    long long sCb, int N, int K)
{
    extern __shared__ __align__(16) char smem[];

    const int tid = threadIdx.x;
    const int wid = tid >> 5;
    const int lid = tid & 31;
    const int warp_m = wid >> 1;      // 0..3 -> 64-row slice
    const int warp_n = wid & 1;       // 0..1 -> 64-col slice
    const int row0 = blockIdx.y * 256;
    const int col0 = blockIdx.x * 128;
    const int z = blockIdx.z;

    const __nv_bfloat16* srcs[4];
    srcs[0] = Ah + (size_t)z * sAb + (size_t)row0 * K;
    srcs[1] = Al + (size_t)z * sAb + (size_t)row0 * K;
    srcs[2] = Bh + (size_t)z * sBb + (size_t)col0 * K;
    srcs[3] = Bl + (size_t)z * sBb + (size_t)col0 * K;

    const uint32_t smb = smem_to_u32(smem);

    // ldmatrix lane addresses (bytes) within a plane
    const int rA = warp_m * 64 + (lid & 15);
    const uint32_t aoff = (uint32_t)(rA * 80 + ((lid >> 4) & 1) * 16);
    const int rB = warp_n * 64 + (lid & 7) + ((lid >> 4) & 1) * 8;
    const uint32_t boff = (uint32_t)(rB * 80 + ((lid >> 3) & 1) * 16);

    float d[4][8][4];
#pragma unroll
    for (int i = 0; i < 4; i++)
#pragma unroll
        for (int j = 0; j < 8; j++)
#pragma unroll
            for (int c = 0; c < 4; c++) d[i][j][c] = 0.f;

    const int nchunks = K >> 5;
    const int ld_c = tid & 3;         // 16B chunk within 64B row payload

    auto issue = [&](int ci, int st) {
        const int k0 = ci << 5;
        const uint32_t sb = smb + st * STAGE_BYTES;
        // A planes: 256 rows x 4 chunks
#pragma unroll
        for (int p = 0; p < 2; p++) {
            const __nv_bfloat16* sp = srcs[p];
            const uint32_t pb = sb + p * A_PLANE_BYTES;
#pragma unroll
            for (int t = 0; t < 4; t++) {
                int r = (tid >> 2) + t * 64;
                cp_async16(pb + r * 80 + ld_c * 16,
                           sp + (size_t)r * K + k0 + ld_c * 8);
            }
        }
        // B planes: 128 rows x 4 chunks
#pragma unroll
        for (int p = 0; p < 2; p++) {
            const __nv_bfloat16* sp = srcs[2 + p];
            const uint32_t pb = sb + 2 * A_PLANE_BYTES + p * B_PLANE_BYTES;
#pragma unroll
            for (int t = 0; t < 2; t++) {
                int r = (tid >> 2) + t * 64;
                cp_async16(pb + r * 80 + ld_c * 16,
                           sp + (size_t)r * K + k0 + ld_c * 8);
            }
        }
        cp_commit();
    };

    issue(0, 0);

    for (int ci = 0; ci < nchunks; ci++) {
        const int st = ci & 1;
        if (ci + 1 < nchunks) {
            issue(ci + 1, st ^ 1);
            cp_wait<1>();
        } else {
            cp_wait<0>();
        }
        __syncthreads();

        const uint32_t sb = smb + st * STAGE_BYTES;
        const uint32_t pAh = sb;
        const uint32_t pAl = sb + A_PLANE_BYTES;
        const uint32_t pBh = sb + 2 * A_PLANE_BYTES;
        const uint32_t pBl = sb + 2 * A_PLANE_BYTES + B_PLANE_BYTES;

#pragma unroll
        for (int ks = 0; ks < 2; ks++) {
            const uint32_t kb = ks * 32;
            uint32_t bh[16], bl[16];
#pragma unroll
            for (int nj = 0; nj < 4; nj++) {
                ldsm_x4(bh + nj * 4, pBh + boff + kb + nj * 1280);
                ldsm_x4(bl + nj * 4, pBl + boff + kb + nj * 1280);
            }
#pragma unroll
            for (int mi = 0; mi < 4; mi++) {
                uint32_t ah[4], al[4];
                ldsm_x4(ah, pAh + aoff + kb + mi * 1280);
                ldsm_x4(al, pAl + aoff + kb + mi * 1280);
#pragma unroll
                for (int ni = 0; ni < 8; ni++) {
                    mma_bf16(d[mi][ni], ah, bh + ni * 2);
                    mma_bf16(d[mi][ni], ah, bl + ni * 2);
                    mma_bf16(d[mi][ni], al, bh + ni * 2);
                }
            }
        }
        __syncthreads();
    }

    // ---- epilogue ----
    const float* bz = (bias2 && z == 1) ? bias2 : bias;
    const int tr = lid >> 2;
    const int tc = (lid & 3) * 2;
#pragma unroll
    for (int mi = 0; mi < 4; mi++) {
        int r0g = row0 + warp_m * 64 + mi * 16 + tr;
#pragma unroll
        for (int ni = 0; ni < 8; ni++) {
            int cg = col0 + warp_n * 64 + ni * 8 + tc;
            if (Cf) {
                float* dst0 = Cf + (size_t)z * sCb + (size_t)r0g * N + cg;
                float* dst1 = dst0 + (size_t)8 * N;
                float2 v0 = make_float2(d[mi][ni][0] * scale, d[mi][ni][1] * scale);
                float2 v1 = make_float2(d[mi][ni][2] * scale, d[mi][ni][3] * scale);
                *(float2*)dst0 = v0;
                *(float2*)dst1 = v1;
            } else {
                float b0 = bz[cg], b1 = bz[cg + 1];
#pragma unroll
                for (int half = 0; half < 2; half++) {
                    float v0 = (d[mi][ni][half * 2 + 0] + b0) * scale;
                    float v1 = (d[mi][ni][half * 2 + 1] + b1) * scale;
                    __nv_bfloat16 h0 = __float2bfloat16(v0);
                    __nv_bfloat16 h1 = __float2bfloat16(v1);
                    __nv_bfloat162 hp; hp.x = h0; hp.y = h1;
                    __nv_bfloat162 lp;
                    lp.x = __float2bfloat16(v0 - __bfloat162float(h0));
                    lp.y = __float2bfloat16(v1 - __bfloat162float(h1));
                    size_t o = (size_t)z * sCb + (size_t)(r0g + half * 8) * N + cg;
                    *(__nv_bfloat162*)(Ch + o) = hp;
                    *(__nv_bfloat162*)(Cl + o) = lp;
                }
            }
        }
    }
}

// ---------------------------------------------------------------------------
extern "C" void kernel_launch(void* const* d_in, const int* in_sizes, int n_in,
                              void* d_out, int out_size)
{
    const float* x  = (const float*)d_in[0];  // [8,2048,512]
    const float* Wq = (const float*)d_in[1];  // [512,512]
    const float* bq = (const float*)d_in[2];  // [512]
    const float* Wk = (const float*)d_in[3];  // [512,512]
    const float* bk = (const float*)d_in[4];  // [512]
    float* out = (float*)d_out;               // [8,2048,512]

    cudaFuncSetAttribute(gemm_bf16x2,
                         cudaFuncAttributeMaxDynamicSharedMemorySize, GSMEM_TOTAL);

    __nv_bfloat16 *xh, *xl, *xTh, *xTl, *WTh, *WTl, *QKh, *QKl, *Ph, *Pl;
    float* Sf;
    cudaGetSymbolAddress((void**)&xh,  g_xh);
    cudaGetSymbolAddress((void**)&xl,  g_xl);
    cudaGetSymbolAddress((void**)&xTh, g_xTh);
    cudaGetSymbolAddress((void**)&xTl, g_xTl);
    cudaGetSymbolAddress((void**)&WTh, g_WTh);
    cudaGetSymbolAddress((void**)&WTl, g_WTl);
    cudaGetSymbolAddress((void**)&QKh, g_QKh);
    cudaGetSymbolAddress((void**)&QKl, g_QKl);
    cudaGetSymbolAddress((void**)&Sf,  g_S);
    cudaGetSymbolAddress((void**)&Ph,  g_Ph);
    cudaGetSymbolAddress((void**)&Pl,  g_Pl);

    const float scaleQ = 1.0f / sqrtf((float)HID);

    // --- prep: splits & transposes ---
    split_planes<<<(MROWS * HID + 255) / 256, 256>>>(x, xh, xl, MROWS * HID);
    {
        dim3 g(HID / 32, HID / 32, 1);
        dim3 b(32, 8);
        transpose_split<<<g, b>>>(Wq, WTh, WTl, HID, HID);
        transpose_split<<<g, b>>>(Wk, WTh + HID * HID, WTl + HID * HID, HID, HID);
    }
    {
        dim3 g(HID / 32, SEQ / 32, BATCH);
        dim3 b(32, 8);
        transpose_split<<<g, b>>>(x, xTh, xTl, SEQ, HID);
    }

    // --- merged Q/K projections: z=0 -> Q, z=1 -> K (M=16384,N=512,K=512) ---
    {
        dim3 grid(HID / 128, MROWS / 256, 2);
        gemm_bf16x2<<<grid, 256, GSMEM_TOTAL>>>(
            xh, xl, 0, WTh, WTl, (long long)HID * HID, bq, bk, 1.0f,
            nullptr, QKh, QKl, (long long)MROWS * HID, HID, HID);
    }
    // --- scores S = (Q@K^T) * 1/sqrt(D) (per batch 2048x2048, K=512) ---
    {
        dim3 grid(SEQ / 128, SEQ / 256, BATCH);
        gemm_bf16x2<<<grid, 256, GSMEM_TOTAL>>>(
            QKh, QKl, (long long)SEQ * HID,
            QKh + (size_t)MROWS * HID, QKl + (size_t)MROWS * HID,
            (long long)SEQ * HID,
            nullptr, nullptr, scaleQ,
            Sf, nullptr, nullptr, (long long)SEQ * SEQ, SEQ, HID);
    }
    // --- softmax -> P planes ---
    softmax_split<<<MROWS, 256>>>(Sf, Ph, Pl);
    // --- out = P @ x (per batch 2048x512, K=2048) ---
    {
        dim3 grid(HID / 128, SEQ / 256, BATCH);
        gemm_bf16x2<<<grid, 256, GSMEM_TOTAL>>>(
            Ph, Pl, (long long)SEQ * SEQ, xTh, xTl, (long long)HID * SEQ,
            nullptr, nullptr, 1.0f,
            out, nullptr, nullptr, (long long)SEQ * HID, HID, SEQ);
    }
}

// round 9
// speedup vs baseline: 1.1234x; 1.1234x over previous
#include <cuda_runtime.h>
#include <cuda_bf16.h>
#include <cstdint>
#include <math.h>

// ===========================================================================
// SelfAttention via mma.sync (HMMA bf16, base sm_103 ISA) with 2-term
// error-compensated splits: X = Xh + Xl (bf16); D = Xh*Yh + Xh*Yl + Xl*Yh.
// R8: R6 GEMM core (64x32 warp tiles, proven fastest) + softmax fused into
// GEMM epilogues (exp in scores epilogue + atomic rowsum; 1/rowsum in out
// epilogue) + fused prep (single pass over x).
// ===========================================================================

#define BATCH 8
#define SEQ   2048
#define HID   512
#define MROWS (BATCH * SEQ)   // 16384

// ---------------- scratch (__device__ globals) ----------------
__device__ __nv_bfloat16 g_xh[MROWS * HID];
__device__ __nv_bfloat16 g_xl[MROWS * HID];
__device__ __nv_bfloat16 g_xTh[MROWS * HID];   // per-batch [512,2048]
__device__ __nv_bfloat16 g_xTl[MROWS * HID];
__device__ __nv_bfloat16 g_WTh[2 * HID * HID]; // slot0 = WqT, slot1 = WkT
__device__ __nv_bfloat16 g_WTl[2 * HID * HID];
__device__ __nv_bfloat16 g_QKh[2 * MROWS * HID];  // slot0 = Q, slot1 = K
__device__ __nv_bfloat16 g_QKl[2 * MROWS * HID];
__device__ __nv_bfloat16 g_Eh[(size_t)BATCH * SEQ * SEQ];   // 64 MB exp planes
__device__ __nv_bfloat16 g_El[(size_t)BATCH * SEQ * SEQ];   // 64 MB
__device__ float         g_rowsum[MROWS];

// ---------------- asm helpers (base ISA) ----------------
__device__ __forceinline__ void ldsm_x4(uint32_t* r, uint32_t addr) {
    asm volatile("ldmatrix.sync.aligned.m8n8.x4.shared.b16 {%0,%1,%2,%3}, [%4];"
                 : "=r"(r[0]), "=r"(r[1]), "=r"(r[2]), "=r"(r[3]) : "r"(addr));
}
__device__ __forceinline__ void mma_bf16(float* d, const uint32_t* a, const uint32_t* b) {
    asm volatile(
        "mma.sync.aligned.m16n8k16.row.col.f32.bf16.bf16.f32 "
        "{%0,%1,%2,%3}, {%4,%5,%6,%7}, {%8,%9}, {%0,%1,%2,%3};"
        : "+f"(d[0]), "+f"(d[1]), "+f"(d[2]), "+f"(d[3])
        : "r"(a[0]), "r"(a[1]), "r"(a[2]), "r"(a[3]), "r"(b[0]), "r"(b[1]));
}
__device__ __forceinline__ uint32_t smem_to_u32(const void* p) {
    uint32_t a;
    asm("{ .reg .u64 t; cvta.to.shared.u64 t, %1; cvt.u32.u64 %0, t; }"
        : "=r"(a) : "l"(p));
    return a;
}
__device__ __forceinline__ void cp_async16(uint32_t dst, const void* src) {
    asm volatile("cp.async.cg.shared.global [%0], [%1], 16;"
                 :: "r"(dst), "l"(src));
}
__device__ __forceinline__ void cp_commit() {
    asm volatile("cp.async.commit_group;");
}
template <int N>
__device__ __forceinline__ void cp_wait() {
    asm volatile("cp.async.wait_group %0;" :: "n"(N));
}

// ---------------- prep ----------------
// One pass over x: direct split -> (xh,xl)  AND  per-batch transpose split
// -> (xTh,xTl). block (32,8), grid (HID/32, SEQ/32, BATCH).
__global__ __launch_bounds__(256) void fused_prep(
    const float* __restrict__ x,
    __nv_bfloat16* __restrict__ xh, __nv_bfloat16* __restrict__ xl,
    __nv_bfloat16* __restrict__ xTh, __nv_bfloat16* __restrict__ xTl)
{
    __shared__ float t[32][33];
    const size_t base = (size_t)blockIdx.z * SEQ * HID;
    const int c0 = blockIdx.x * 32;   // hid
    const int r0 = blockIdx.y * 32;   // seq
    const int tx = threadIdx.x, ty = threadIdx.y;

#pragma unroll
    for (int j = 0; j < 4; j++) {
        int r = r0 + ty + j * 8;
        size_t o = base + (size_t)r * HID + c0 + tx;
        float v = x[o];
        t[ty + j * 8][tx] = v;
        __nv_bfloat16 hi = __float2bfloat16(v);
        xh[o] = hi;
        xl[o] = __float2bfloat16(v - __bfloat162float(hi));
    }
    __syncthreads();
#pragma unroll
    for (int j = 0; j < 4; j++) {
        float v = t[tx][ty + j * 8];             // seq=r0+tx, hid=c0+ty+j*8
        __nv_bfloat16 hi = __float2bfloat16(v);
        size_t o = base + (size_t)(c0 + ty + j * 8) * SEQ + r0 + tx;
        xTh[o] = hi;
        xTl[o] = __float2bfloat16(v - __bfloat162float(hi));
    }
}

// transpose+split for W (fp32 [R,C] -> planes [C,R])
__global__ __launch_bounds__(256) void transpose_split(
    const float* __restrict__ src, __nv_bfloat16* __restrict__ h,
    __nv_bfloat16* __restrict__ l, int R, int C)
{
    __shared__ float t[32][33];
    size_t base = (size_t)blockIdx.z * R * C;
    int c0 = blockIdx.x * 32, r0 = blockIdx.y * 32;
    int tx = threadIdx.x, ty = threadIdx.y;
#pragma unroll
    for (int j = 0; j < 4; j++)
        t[ty + j * 8][tx] = src[base + (size_t)(r0 + ty + j * 8) * C + c0 + tx];
    __syncthreads();
#pragma unroll
    for (int j = 0; j < 4; j++) {
        float v = t[tx][ty + j * 8];
        __nv_bfloat16 hi = __float2bfloat16(v);
        size_t o = base + (size_t)(c0 + ty + j * 8) * R + r0 + tx;
        h[o] = hi;
        l[o] = __float2bfloat16(v - __bfloat162float(hi));
    }
}

__global__ void zero_rowsum(float* __restrict__ rs)
{
    rs[blockIdx.x * 256 + threadIdx.x] = 0.f;
}

// ===========================================================================
// HMMA GEMM (R6 core): CTA 128x128, warp tile 64x32 (warp_m=wid&1,
// warp_n=wid>>1), K-chunk 32, 2-stage cp.async.
// Epilogue modes:
//   Cf && !rowsum : fp32 = d*scale
//   Cf &&  rowsum : fp32 = d / rowsum[row]          (out GEMM)
//  !Cf && !rowsum : (d + bias[z])*scale -> planes   (projections)
//  !Cf &&  rowsum : e = expf(d*scale) -> planes, atomicAdd rowsum (scores)
// ===========================================================================
#define PLANE_BYTES (128 * 80)            // 10240
#define STAGE_BYTES (4 * PLANE_BYTES)     // 40960
#define GSMEM_TOTAL (2 * STAGE_BYTES)     // 81920

__global__ __launch_bounds__(256) void gemm_bf16x2(
    const __nv_bfloat16* __restrict__ Ah, const __nv_bfloat16* __restrict__ Al,
    long long sAb,
    const __nv_bfloat16* __restrict__ Bh, const __nv_bfloat16* __restrict__ Bl,
    long long sBb,
    const float* __restrict__ bias, const float* __restrict__ bias2,
    float scale,
    float* __restrict__ Cf,
    __nv_bfloat16* __restrict__ Ch, __nv_bfloat16* __restrict__ Cl,
    float* __restrict__ rowsum,
    long long sCb, int N, int K)
{
    extern __shared__ __align__(16) char smem[];

    const int tid = threadIdx.x;
    const int wid = tid >> 5;
    const int lid = tid & 31;
    const int warp_m = wid & 1;
    const int warp_n = wid >> 1;
    const int row0 = blockIdx.y * 128;
    const int col0 = blockIdx.x * 128;
    const int z = blockIdx.z;

    const __nv_bfloat16* srcs[4];
    srcs[0] = Ah + (size_t)z * sAb + (size_t)row0 * K;
    srcs[1] = Al + (size_t)z * sAb + (size_t)row0 * K;
    srcs[2] = Bh + (size_t)z * sBb + (size_t)col0 * K;
    srcs[3] = Bl + (size_t)z * sBb + (size_t)col0 * K;

    const uint32_t smb = smem_to_u32(smem);

    const int ld_r0 = tid >> 2;
    const int ld_ch = tid & 3;

    const int rA = warp_m * 64 + (lid & 7) + ((lid >> 3) & 1) * 8;
    const uint32_t aoff = (uint32_t)(rA * 80 + ((lid >> 4) & 1) * 16);
    const int rB = warp_n * 32 + (lid & 7) + ((lid >> 4) & 1) * 8;
    const uint32_t boff = (uint32_t)(rB * 80 + ((lid >> 3) & 1) * 16);

    float d[4][4][4];
#pragma unroll
    for (int i = 0; i < 4; i++)
#pragma unroll
        for (int j = 0; j < 4; j++)
#pragma unroll
            for (int c = 0; c < 4; c++) d[i][j][c] = 0.f;

    const int nchunks = K >> 5;

    auto issue = [&](int ci, int st) {
        const int k0 = ci << 5;
        const uint32_t sb = smb + st * STAGE_BYTES;
#pragma unroll
        for (int p = 0; p < 4; p++) {
            const __nv_bfloat16* sp = srcs[p];
            const uint32_t pb = sb + p * PLANE_BYTES;
#pragma unroll
            for (int t = 0; t < 2; t++) {
                int r = ld_r0 + t * 64;
                cp_async16(pb + r * 80 + ld_ch * 16,
                           sp + (size_t)r * K + k0 + ld_ch * 8);
            }
        }
        cp_commit();
    };

    issue(0, 0);

    for (int ci = 0; ci < nchunks; ci++) {
        const int st = ci & 1;
        if (ci + 1 < nchunks) {
            issue(ci + 1, st ^ 1);
            cp_wait<1>();
        } else {
            cp_wait<0>();
        }
        __syncthreads();

        const uint32_t sb = smb + st * STAGE_BYTES;
        const uint32_t pAh = sb;
        const uint32_t pAl = sb + 1 * PLANE_BYTES;
        const uint32_t pBh = sb + 2 * PLANE_BYTES;
        const uint32_t pBl = sb + 3 * PLANE_BYTES;

#pragma unroll
        for (int ks = 0; ks < 2; ks++) {
            const uint32_t kb = ks * 32;
            uint32_t bh[8], bl[8];
            ldsm_x4(bh + 0, pBh + boff + kb);
            ldsm_x4(bh + 4, pBh + boff + kb + 1280);
            ldsm_x4(bl + 0, pBl + boff + kb);
            ldsm_x4(bl + 4, pBl + boff + kb + 1280);
#pragma unroll
            for (int mi = 0; mi < 4; mi++) {
                uint32_t ah[4], al[4];
                ldsm_x4(ah, pAh + aoff + kb + mi * 1280);
                ldsm_x4(al, pAl + aoff + kb + mi * 1280);
#pragma unroll
                for (int ni = 0; ni < 4; ni++) {
                    mma_bf16(d[mi][ni], ah, bh + ni * 2);
                    mma_bf16(d[mi][ni], ah, bl + ni * 2);
                    mma_bf16(d[mi][ni], al, bh + ni * 2);
                }
            }
        }
        __syncthreads();
    }

    // ---- epilogue ----
    const int tr = lid >> 2;
    const int tc = (lid & 3) * 2;

    if (Cf && rowsum) {
        // out GEMM: normalize by rowsum
#pragma unroll
        for (int mi = 0; mi < 4; mi++) {
            int r0g = row0 + warp_m * 64 + mi * 16 + tr;
            float inv0 = 1.0f / rowsum[z * SEQ + r0g];
            float inv1 = 1.0f / rowsum[z * SEQ + r0g + 8];
#pragma unroll
            for (int ni = 0; ni < 4; ni++) {
                int cg = col0 + warp_n * 32 + ni * 8 + tc;
                float* dst0 = Cf + (size_t)z * sCb + (size_t)r0g * N + cg;
                float* dst1 = dst0 + (size_t)8 * N;
                *(float2*)dst0 = make_float2(d[mi][ni][0] * inv0, d[mi][ni][1] * inv0);
                *(float2*)dst1 = make_float2(d[mi][ni][2] * inv1, d[mi][ni][3] * inv1);
            }
        }
    } else if (Cf) {
#pragma unroll
        for (int mi = 0; mi < 4; mi++) {
            int r0g = row0 + warp_m * 64 + mi * 16 + tr;
#pragma unroll
            for (int ni = 0; ni < 4; ni++) {
                int cg = col0 + warp_n * 32 + ni * 8 + tc;
                float* dst0 = Cf + (size_t)z * sCb + (size_t)r0g * N + cg;
                float* dst1 = dst0 + (size_t)8 * N;
                *(float2*)dst0 = make_float2(d[mi][ni][0] * scale, d[mi][ni][1] * scale);
                *(float2*)dst1 = make_float2(d[mi][ni][2] * scale, d[mi][ni][3] * scale);
            }
        }
    } else if (rowsum) {
        // scores GEMM: e = exp(d*scale) -> planes, accumulate row sums
        float rs[4][2];
#pragma unroll
        for (int mi = 0; mi < 4; mi++) { rs[mi][0] = 0.f; rs[mi][1] = 0.f; }
#pragma unroll
        for (int mi = 0; mi < 4; mi++) {
            int r0g = row0 + warp_m * 64 + mi * 16 + tr;
#pragma unroll
            for (int ni = 0; ni < 4; ni++) {
                int cg = col0 + warp_n * 32 + ni * 8 + tc;
                float e0 = __expf(d[mi][ni][0] * scale);
                float e1 = __expf(d[mi][ni][1] * scale);
                float e2 = __expf(d[mi][ni][2] * scale);
                float e3 = __expf(d[mi][ni][3] * scale);
                rs[mi][0] += e0 + e1;
                rs[mi][1] += e2 + e3;
                __nv_bfloat16 h0 = __float2bfloat16(e0);
                __nv_bfloat16 h1 = __float2bfloat16(e1);
                __nv_bfloat16 h2 = __float2bfloat16(e2);
                __nv_bfloat16 h3 = __float2bfloat16(e3);
                __nv_bfloat162 hp0; hp0.x = h0; hp0.y = h1;
                __nv_bfloat162 hp1; hp1.x = h2; hp1.y = h3;
                __nv_bfloat162 lp0, lp1;
                lp0.x = __float2bfloat16(e0 - __bfloat162float(h0));
                lp0.y = __float2bfloat16(e1 - __bfloat162float(h1));
                lp1.x = __float2bfloat16(e2 - __bfloat162float(h2));
                lp1.y = __float2bfloat16(e3 - __bfloat162float(h3));
                size_t o0 = (size_t)z * sCb + (size_t)r0g * N + cg;
                size_t o1 = o0 + (size_t)8 * N;
                *(__nv_bfloat162*)(Ch + o0) = hp0;
                *(__nv_bfloat162*)(Cl + o0) = lp0;
                *(__nv_bfloat162*)(Ch + o1) = hp1;
                *(__nv_bfloat162*)(Cl + o1) = lp1;
            }
        }
        // reduce across the 4 lanes sharing each row (lid&3), then atomicAdd
#pragma unroll
        for (int mi = 0; mi < 4; mi++) {
#pragma unroll
            for (int h = 0; h < 2; h++) {
                float v = rs[mi][h];
                v += __shfl_xor_sync(0xffffffff, v, 1);
                v += __shfl_xor_sync(0xffffffff, v, 2);
                if ((lid & 3) == 0) {
                    int r = row0 + warp_m * 64 + mi * 16 + tr + h * 8;
                    atomicAdd(rowsum + z * SEQ + r, v);
                }
            }
        }
    } else {
        // projection: (d + bias[z])*scale -> planes
        const float* bz = (bias2 && z == 1) ? bias2 : bias;
#pragma unroll
        for (int mi = 0; mi < 4; mi++) {
            int r0g = row0 + warp_m * 64 + mi * 16 + tr;
#pragma unroll
            for (int ni = 0; ni < 4; ni++) {
                int cg = col0 + warp_n * 32 + ni * 8 + tc;
                float b0 = bz[cg], b1 = bz[cg + 1];
#pragma unroll
                for (int half = 0; half < 2; half++) {
                    float v0 = (d[mi][ni][half * 2 + 0] + b0) * scale;
                    float v1 = (d[mi][ni][half * 2 + 1] + b1) * scale;
                    __nv_bfloat16 h0 = __float2bfloat16(v0);
                    __nv_bfloat16 h1 = __float2bfloat16(v1);
                    __nv_bfloat162 hp; hp.x = h0; hp.y = h1;
                    __nv_bfloat162 lp;
                    lp.x = __float2bfloat16(v0 - __bfloat162float(h0));
                    lp.y = __float2bfloat16(v1 - __bfloat162float(h1));
                    size_t o = (size_t)z * sCb + (size_t)(r0g + half * 8) * N + cg;
                    *(__nv_bfloat162*)(Ch + o) = hp;
                    *(__nv_bfloat162*)(Cl + o) = lp;
                }
            }
        }
    }
}

// ---------------------------------------------------------------------------
extern "C" void kernel_launch(void* const* d_in, const int* in_sizes, int n_in,
                              void* d_out, int out_size)
{
    const float* x  = (const float*)d_in[0];  // [8,2048,512]
    const float* Wq = (const float*)d_in[1];  // [512,512]
    const float* bq = (const float*)d_in[2];  // [512]
    const float* Wk = (const float*)d_in[3];  // [512,512]
    const float* bk = (const float*)d_in[4];  // [512]
    float* out = (float*)d_out;               // [8,2048,512]

    cudaFuncSetAttribute(gemm_bf16x2,
                         cudaFuncAttributeMaxDynamicSharedMemorySize, GSMEM_TOTAL);

    __nv_bfloat16 *xh, *xl, *xTh, *xTl, *WTh, *WTl, *QKh, *QKl, *Eh, *El;
    float* rowsum;
    cudaGetSymbolAddress((void**)&xh,  g_xh);
    cudaGetSymbolAddress((void**)&xl,  g_xl);
    cudaGetSymbolAddress((void**)&xTh, g_xTh);
    cudaGetSymbolAddress((void**)&xTl, g_xTl);
    cudaGetSymbolAddress((void**)&WTh, g_WTh);
    cudaGetSymbolAddress((void**)&WTl, g_WTl);
    cudaGetSymbolAddress((void**)&QKh, g_QKh);
    cudaGetSymbolAddress((void**)&QKl, g_QKl);
    cudaGetSymbolAddress((void**)&Eh,  g_Eh);
    cudaGetSymbolAddress((void**)&El,  g_El);
    cudaGetSymbolAddress((void**)&rowsum, g_rowsum);

    const float scaleQ = 1.0f / sqrtf((float)HID);

    // --- prep ---
    {
        dim3 g(HID / 32, SEQ / 32, BATCH);
        dim3 b(32, 8);
        fused_prep<<<g, b>>>(x, xh, xl, xTh, xTl);
    }
    {
        dim3 g(HID / 32, HID / 32, 1);
        dim3 b(32, 8);
        transpose_split<<<g, b>>>(Wq, WTh, WTl, HID, HID);
        transpose_split<<<g, b>>>(Wk, WTh + HID * HID, WTl + HID * HID, HID, HID);
    }
    zero_rowsum<<<MROWS / 256, 256>>>(rowsum);

    // --- merged Q/K projections: z=0 -> Q, z=1 -> K (M=16384,N=512,K=512) ---
    {
        dim3 grid(HID / 128, MROWS / 128, 2);
        gemm_bf16x2<<<grid, 256, GSMEM_TOTAL>>>(
            xh, xl, 0, WTh, WTl, (long long)HID * HID, bq, bk, 1.0f,
            nullptr, QKh, QKl, nullptr, (long long)MROWS * HID, HID, HID);
    }
    // --- scores+exp: E = exp((Q@K^T)/sqrt(D)) -> planes + rowsum ---
    {
        dim3 grid(SEQ / 128, SEQ / 128, BATCH);
        gemm_bf16x2<<<grid, 256, GSMEM_TOTAL>>>(
            QKh, QKl, (long long)SEQ * HID,
            QKh + (size_t)MROWS * HID, QKl + (size_t)MROWS * HID,
            (long long)SEQ * HID,
            nullptr, nullptr, scaleQ,
            nullptr, Eh, El, rowsum, (long long)SEQ * SEQ, SEQ, HID);
    }
    // --- out = (E @ x) / rowsum  (per batch 2048x512, K=2048) ---
    {
        dim3 grid(HID / 128, SEQ / 128, BATCH);
        gemm_bf16x2<<<grid, 256, GSMEM_TOTAL>>>(
            Eh, El, (long long)SEQ * SEQ, xTh, xTl, (long long)HID * SEQ,
            nullptr, nullptr, 1.0f,
            out, nullptr, nullptr, rowsum, (long long)SEQ * HID, HID, SEQ);
    }
}

// round 10
// speedup vs baseline: 1.7167x; 1.5280x over previous
#include <cuda_runtime.h>
#include <cuda_fp16.h>
#include <cstdint>
#include <math.h>

// ===========================================================================
// SelfAttention, fp16-operand HMMA pipeline (base sm_103 ISA).
// HMMA multiplies fp16 exactly into fp32 accumulators, so error = input
// rounding only. fp16 (11-bit mantissa) single planes for Q,K,E give
// ~3.6e-4 rms output error vs the 1e-3 gate. x keeps an fp16 hi/lo split
// for the out-GEMM (2-combo) as a safety anchor.
//   proj:   Q|K = x_f16 @ W_f16^T + b        (1 combo)  -> fp16
//   scores: E = exp((Q@K^T)/sqrt(D))         (1 combo)  -> fp16 + rowsum
//   out:    out = (E @ (xh+xl)) / rowsum     (2 combos) -> fp32
// ===========================================================================

#define BATCH 8
#define SEQ   2048
#define HID   512
#define MROWS (BATCH * SEQ)   // 16384

// ---------------- scratch (__device__ globals) ----------------
__device__ __half g_xf [MROWS * HID];          // x fp16 (proj A operand)
__device__ __half g_xTh[MROWS * HID];          // per-batch [512,2048] hi
__device__ __half g_xTl[MROWS * HID];          // lo
__device__ __half g_WT [2 * HID * HID];        // slot0 WqT, slot1 WkT
__device__ __half g_QKf[2 * (size_t)MROWS * HID];  // slot0 Q, slot1 K
__device__ __half g_Ef [(size_t)BATCH * SEQ * SEQ]; // 67 MB exp(S) fp16
__device__ float  g_rowsum[MROWS];

// ---------------- asm helpers (base ISA) ----------------
__device__ __forceinline__ void ldsm_x4(uint32_t* r, uint32_t addr) {
    asm volatile("ldmatrix.sync.aligned.m8n8.x4.shared.b16 {%0,%1,%2,%3}, [%4];"
                 : "=r"(r[0]), "=r"(r[1]), "=r"(r[2]), "=r"(r[3]) : "r"(addr));
}
__device__ __forceinline__ void mma_f16(float* d, const uint32_t* a, const uint32_t* b) {
    asm volatile(
        "mma.sync.aligned.m16n8k16.row.col.f32.f16.f16.f32 "
        "{%0,%1,%2,%3}, {%4,%5,%6,%7}, {%8,%9}, {%0,%1,%2,%3};"
        : "+f"(d[0]), "+f"(d[1]), "+f"(d[2]), "+f"(d[3])
        : "r"(a[0]), "r"(a[1]), "r"(a[2]), "r"(a[3]), "r"(b[0]), "r"(b[1]));
}
__device__ __forceinline__ uint32_t smem_to_u32(const void* p) {
    uint32_t a;
    asm("{ .reg .u64 t; cvta.to.shared.u64 t, %1; cvt.u32.u64 %0, t; }"
        : "=r"(a) : "l"(p));
    return a;
}
__device__ __forceinline__ void cp_async16(uint32_t dst, const void* src) {
    asm volatile("cp.async.cg.shared.global [%0], [%1], 16;"
                 :: "r"(dst), "l"(src));
}
__device__ __forceinline__ void cp_commit() {
    asm volatile("cp.async.commit_group;");
}
template <int N>
__device__ __forceinline__ void cp_wait() {
    asm volatile("cp.async.wait_group %0;" :: "n"(N));
}

// ---------------- prep ----------------
// One pass over x: fp16 direct plane + per-batch transposed fp16 hi/lo
// planes + rowsum zero-fill. block (32,8), grid (HID/32, SEQ/32, BATCH).
__global__ __launch_bounds__(256) void fused_prep(
    const float* __restrict__ x, __half* __restrict__ xf,
    __half* __restrict__ xTh, __half* __restrict__ xTl,
    float* __restrict__ rowsum)
{
    __shared__ float t[32][33];
    const size_t base = (size_t)blockIdx.z * SEQ * HID;
    const int c0 = blockIdx.x * 32;   // hid
    const int r0 = blockIdx.y * 32;   // seq
    const int tx = threadIdx.x, ty = threadIdx.y;

#pragma unroll
    for (int j = 0; j < 4; j++) {
        int r = r0 + ty + j * 8;
        size_t o = base + (size_t)r * HID + c0 + tx;
        float v = x[o];
        t[ty + j * 8][tx] = v;
        xf[o] = __float2half_rn(v);
    }
    // zero rowsum: 64 y-blocks x 256 threads = 16384
    if (blockIdx.x == 0 && blockIdx.z == 0)
        rowsum[blockIdx.y * 256 + ty * 32 + tx] = 0.f;
    __syncthreads();
#pragma unroll
    for (int j = 0; j < 4; j++) {
        float v = t[tx][ty + j * 8];             // seq=r0+tx, hid=c0+ty+j*8
        __half h = __float2half_rn(v);
        size_t o = base + (size_t)(c0 + ty + j * 8) * SEQ + r0 + tx;
        xTh[o] = h;
        xTl[o] = __float2half_rn(v - __half2float(h));
    }
}

// W transpose -> fp16, both weights in one launch (z selects).
__global__ __launch_bounds__(256) void transpose_w(
    const float* __restrict__ Wq, const float* __restrict__ Wk,
    __half* __restrict__ WT)
{
    __shared__ float t[32][33];
    const float* src = blockIdx.z ? Wk : Wq;
    __half* dst = WT + (size_t)blockIdx.z * HID * HID;
    int c0 = blockIdx.x * 32, r0 = blockIdx.y * 32;
    int tx = threadIdx.x, ty = threadIdx.y;
#pragma unroll
    for (int j = 0; j < 4; j++)
        t[ty + j * 8][tx] = src[(size_t)(r0 + ty + j * 8) * HID + c0 + tx];
    __syncthreads();
#pragma unroll
    for (int j = 0; j < 4; j++)
        dst[(size_t)(c0 + ty + j * 8) * HID + r0 + tx] =
            __float2half_rn(t[tx][ty + j * 8]);
}

// ===========================================================================
// fp16 HMMA GEMM: C[M,N] = A[M,K] @ (B (+ B2))[N,K]^T, fp32 accum.
// CTA 128x128, warp tile 64x32 (warp_m=wid&1, warp_n=wid>>1), K-chunk 32,
// 2-stage cp.async. A single plane; B optionally two planes (2 combos).
// Epilogues: Ch&&!rowsum: (d+bias[z]) -> fp16   (projections)
//            Ch&&rowsum:  exp(d*scale) -> fp16 + atomic rowsum (scores)
//            Cf&&rowsum:  d / rowsum[row] -> fp32 (out)
// ===========================================================================
#define PLANE_BYTES (128 * 80)            // 10240 (64B payload + 16B pad)
#define STAGE_BYTES (3 * PLANE_BYTES)     // 30720 (3rd plane may be unused)
#define GSMEM_TOTAL (2 * STAGE_BYTES)     // 61440

__global__ __launch_bounds__(256) void gemm_f16(
    const __half* __restrict__ Ap, long long sAb,
    const __half* __restrict__ Bp, const __half* __restrict__ Bp2,
    long long sBb,
    const float* __restrict__ bias, const float* __restrict__ bias2,
    float scale,
    float* __restrict__ Cf, __half* __restrict__ Ch,
    float* __restrict__ rowsum,
    long long sCb, int N, int K)
{
    extern __shared__ __align__(16) char smem[];

    const int tid = threadIdx.x;
    const int wid = tid >> 5;
    const int lid = tid & 31;
    const int warp_m = wid & 1;
    const int warp_n = wid >> 1;
    const int row0 = blockIdx.y * 128;
    const int col0 = blockIdx.x * 128;
    const int z = blockIdx.z;

    const __half* srcs[3];
    srcs[0] = Ap + (size_t)z * sAb + (size_t)row0 * K;
    srcs[1] = Bp + (size_t)z * sBb + (size_t)col0 * K;
    srcs[2] = Bp2 ? Bp2 + (size_t)z * sBb + (size_t)col0 * K : nullptr;
    const int nplanes = Bp2 ? 3 : 2;

    const uint32_t smb = smem_to_u32(smem);
    const int ld_r0 = tid >> 2;
    const int ld_ch = tid & 3;

    const int rA = warp_m * 64 + (lid & 7) + ((lid >> 3) & 1) * 8;
    const uint32_t aoff = (uint32_t)(rA * 80 + ((lid >> 4) & 1) * 16);
    const int rB = warp_n * 32 + (lid & 7) + ((lid >> 4) & 1) * 8;
    const uint32_t boff = (uint32_t)(rB * 80 + ((lid >> 3) & 1) * 16);

    float d[4][4][4];
#pragma unroll
    for (int i = 0; i < 4; i++)
#pragma unroll
        for (int j = 0; j < 4; j++)
#pragma unroll
            for (int c = 0; c < 4; c++) d[i][j][c] = 0.f;

    const int nchunks = K >> 5;

    auto issue = [&](int ci, int st) {
        const int k0 = ci << 5;
        const uint32_t sb = smb + st * STAGE_BYTES;
        for (int p = 0; p < nplanes; p++) {
            const __half* sp = srcs[p];
            const uint32_t pb = sb + p * PLANE_BYTES;
#pragma unroll
            for (int t = 0; t < 2; t++) {
                int r = ld_r0 + t * 64;
                cp_async16(pb + r * 80 + ld_ch * 16,
                           sp + (size_t)r * K + k0 + ld_ch * 8);
            }
        }
        cp_commit();
    };

    issue(0, 0);

    for (int ci = 0; ci < nchunks; ci++) {
        const int st = ci & 1;
        if (ci + 1 < nchunks) {
            issue(ci + 1, st ^ 1);
            cp_wait<1>();
        } else {
            cp_wait<0>();
        }
        __syncthreads();

        const uint32_t sb = smb + st * STAGE_BYTES;
        const uint32_t pA  = sb;
        const uint32_t pB  = sb + PLANE_BYTES;
        const uint32_t pB2 = sb + 2 * PLANE_BYTES;

#pragma unroll
        for (int ks = 0; ks < 2; ks++) {
            const uint32_t kb = ks * 32;
            uint32_t bh[8], bl[8];
            ldsm_x4(bh + 0, pB + boff + kb);
            ldsm_x4(bh + 4, pB + boff + kb + 1280);
            if (Bp2) {
                ldsm_x4(bl + 0, pB2 + boff + kb);
                ldsm_x4(bl + 4, pB2 + boff + kb + 1280);
            }
#pragma unroll
            for (int mi = 0; mi < 4; mi++) {
                uint32_t ah[4];
                ldsm_x4(ah, pA + aoff + kb + mi * 1280);
#pragma unroll
                for (int ni = 0; ni < 4; ni++)
                    mma_f16(d[mi][ni], ah, bh + ni * 2);
                if (Bp2) {
#pragma unroll
                    for (int ni = 0; ni < 4; ni++)
                        mma_f16(d[mi][ni], ah, bl + ni * 2);
                }
            }
        }
        __syncthreads();
    }

    // ---- epilogue ----
    const int tr = lid >> 2;
    const int tc = (lid & 3) * 2;

    if (Cf) {
        // out GEMM: normalize by rowsum
#pragma unroll
        for (int mi = 0; mi < 4; mi++) {
            int r0g = row0 + warp_m * 64 + mi * 16 + tr;
            float inv0 = 1.0f / rowsum[z * SEQ + r0g];
            float inv1 = 1.0f / rowsum[z * SEQ + r0g + 8];
#pragma unroll
            for (int ni = 0; ni < 4; ni++) {
                int cg = col0 + warp_n * 32 + ni * 8 + tc;
                float* dst0 = Cf + (size_t)z * sCb + (size_t)r0g * N + cg;
                float* dst1 = dst0 + (size_t)8 * N;
                *(float2*)dst0 = make_float2(d[mi][ni][0] * inv0, d[mi][ni][1] * inv0);
                *(float2*)dst1 = make_float2(d[mi][ni][2] * inv1, d[mi][ni][3] * inv1);
            }
        }
    } else if (rowsum) {
        // scores: e = exp(d*scale) -> fp16, accumulate row sums
        float rs[4][2];
#pragma unroll
        for (int mi = 0; mi < 4; mi++) { rs[mi][0] = 0.f; rs[mi][1] = 0.f; }
#pragma unroll
        for (int mi = 0; mi < 4; mi++) {
            int r0g = row0 + warp_m * 64 + mi * 16 + tr;
#pragma unroll
            for (int ni = 0; ni < 4; ni++) {
                int cg = col0 + warp_n * 32 + ni * 8 + tc;
                float e0 = __expf(d[mi][ni][0] * scale);
                float e1 = __expf(d[mi][ni][1] * scale);
                float e2 = __expf(d[mi][ni][2] * scale);
                float e3 = __expf(d[mi][ni][3] * scale);
                rs[mi][0] += e0 + e1;
                rs[mi][1] += e2 + e3;
                __half2 p0; p0.x = __float2half_rn(e0); p0.y = __float2half_rn(e1);
                __half2 p1; p1.x = __float2half_rn(e2); p1.y = __float2half_rn(e3);
                size_t o0 = (size_t)z * sCb + (size_t)r0g * N + cg;
                *(__half2*)(Ch + o0) = p0;
                *(__half2*)(Ch + o0 + (size_t)8 * N) = p1;
            }
        }
#pragma unroll
        for (int mi = 0; mi < 4; mi++) {
#pragma unroll
            for (int h = 0; h < 2; h++) {
                float v = rs[mi][h];
                v += __shfl_xor_sync(0xffffffff, v, 1);
                v += __shfl_xor_sync(0xffffffff, v, 2);
                if ((lid & 3) == 0) {
                    int r = row0 + warp_m * 64 + mi * 16 + tr + h * 8;
                    atomicAdd(rowsum + z * SEQ + r, v);
                }
            }
        }
    } else {
        // projection: d + bias[z] -> fp16
        const float* bz = (bias2 && z == 1) ? bias2 : bias;
#pragma unroll
        for (int mi = 0; mi < 4; mi++) {
            int r0g = row0 + warp_m * 64 + mi * 16 + tr;
#pragma unroll
            for (int ni = 0; ni < 4; ni++) {
                int cg = col0 + warp_n * 32 + ni * 8 + tc;
                float b0 = bz[cg], b1 = bz[cg + 1];
#pragma unroll
                for (int half = 0; half < 2; half++) {
                    __half2 p;
                    p.x = __float2half_rn(d[mi][ni][half * 2 + 0] + b0);
                    p.y = __float2half_rn(d[mi][ni][half * 2 + 1] + b1);
                    size_t o = (size_t)z * sCb + (size_t)(r0g + half * 8) * N + cg;
                    *(__half2*)(Ch + o) = p;
                }
            }
        }
    }
}

// ---------------------------------------------------------------------------
extern "C" void kernel_launch(void* const* d_in, const int* in_sizes, int n_in,
                              void* d_out, int out_size)
{
    const float* x  = (const float*)d_in[0];  // [8,2048,512]
    const float* Wq = (const float*)d_in[1];  // [512,512]
    const float* bq = (const float*)d_in[2];  // [512]
    const float* Wk = (const float*)d_in[3];  // [512,512]
    const float* bk = (const float*)d_in[4];  // [512]
    float* out = (float*)d_out;               // [8,2048,512]

    cudaFuncSetAttribute(gemm_f16,
                         cudaFuncAttributeMaxDynamicSharedMemorySize, GSMEM_TOTAL);

    __half *xf, *xTh, *xTl, *WT, *QKf, *Ef;
    float* rowsum;
    cudaGetSymbolAddress((void**)&xf,  g_xf);
    cudaGetSymbolAddress((void**)&xTh, g_xTh);
    cudaGetSymbolAddress((void**)&xTl, g_xTl);
    cudaGetSymbolAddress((void**)&WT,  g_WT);
    cudaGetSymbolAddress((void**)&QKf, g_QKf);
    cudaGetSymbolAddress((void**)&Ef,  g_Ef);
    cudaGetSymbolAddress((void**)&rowsum, g_rowsum);

    const float scaleQ = 1.0f / sqrtf((float)HID);

    // --- prep ---
    {
        dim3 g(HID / 32, SEQ / 32, BATCH);
        dim3 b(32, 8);
        fused_prep<<<g, b>>>(x, xf, xTh, xTl, rowsum);
    }
    {
        dim3 g(HID / 32, HID / 32, 2);
        dim3 b(32, 8);
        transpose_w<<<g, b>>>(Wq, Wk, WT);
    }

    // --- merged Q/K projections (1 combo): z=0->Q, z=1->K ---
    {
        dim3 grid(HID / 128, MROWS / 128, 2);
        gemm_f16<<<grid, 256, GSMEM_TOTAL>>>(
            xf, 0, WT, nullptr, (long long)HID * HID,
            bq, bk, 1.0f,
            nullptr, QKf, nullptr, (long long)MROWS * HID, HID, HID);
    }
    // --- scores+exp (1 combo): E = exp((Q@K^T)/sqrt(D)) -> fp16 + rowsum ---
    {
        dim3 grid(SEQ / 128, SEQ / 128, BATCH);
        gemm_f16<<<grid, 256, GSMEM_TOTAL>>>(
            QKf, (long long)SEQ * HID,
            QKf + (size_t)MROWS * HID, nullptr, (long long)SEQ * HID,
            nullptr, nullptr, scaleQ,
            nullptr, Ef, rowsum, (long long)SEQ * SEQ, SEQ, HID);
    }
    // --- out (2 combos): out = (E @ (xh+xl)) / rowsum ---
    {
        dim3 grid(HID / 128, SEQ / 128, BATCH);
        gemm_f16<<<grid, 256, GSMEM_TOTAL>>>(
            Ef, (long long)SEQ * SEQ,
            xTh, xTl, (long long)HID * SEQ,
            nullptr, nullptr, 1.0f,
            out, nullptr, rowsum, (long long)SEQ * HID, HID, SEQ);
    }
}

// round 11
// speedup vs baseline: 2.4593x; 1.4326x over previous
#include <cuda_runtime.h>
#include <cuda_fp16.h>
#include <cstdint>
#include <math.h>

// ===========================================================================
// SelfAttention, fp16-operand HMMA pipeline (base sm_103 ISA).
// HMMA multiplies fp16 exactly into fp32 accumulators; error = input
// rounding only (~2.8e-4 rms per fp16-rounded operand, uncorrelated).
// R10: ALL GEMMs single-combo fp16 (out-GEMM dropped its hi/lo x split).
//   proj:   Q|K = x_f16 @ W_f16^T + b        -> fp16
//   scores: E = exp((Q@K^T)/sqrt(D))         -> fp16 + rowsum
//   out:    out = (E @ xT^T) / rowsum        -> fp32
// ===========================================================================

#define BATCH 8
#define SEQ   2048
#define HID   512
#define MROWS (BATCH * SEQ)   // 16384

// ---------------- scratch (__device__ globals) ----------------
__device__ __half g_xf [MROWS * HID];          // x fp16 (proj A operand)
__device__ __half g_xT [MROWS * HID];          // per-batch [512,2048] fp16
__device__ __half g_WT [2 * HID * HID];        // slot0 WqT, slot1 WkT
__device__ __half g_QKf[2 * (size_t)MROWS * HID];  // slot0 Q, slot1 K
__device__ __half g_Ef [(size_t)BATCH * SEQ * SEQ]; // 67 MB exp(S) fp16
__device__ float  g_rowsum[MROWS];

// ---------------- asm helpers (base ISA) ----------------
__device__ __forceinline__ void ldsm_x4(uint32_t* r, uint32_t addr) {
    asm volatile("ldmatrix.sync.aligned.m8n8.x4.shared.b16 {%0,%1,%2,%3}, [%4];"
                 : "=r"(r[0]), "=r"(r[1]), "=r"(r[2]), "=r"(r[3]) : "r"(addr));
}
__device__ __forceinline__ void mma_f16(float* d, const uint32_t* a, const uint32_t* b) {
    asm volatile(
        "mma.sync.aligned.m16n8k16.row.col.f32.f16.f16.f32 "
        "{%0,%1,%2,%3}, {%4,%5,%6,%7}, {%8,%9}, {%0,%1,%2,%3};"
        : "+f"(d[0]), "+f"(d[1]), "+f"(d[2]), "+f"(d[3])
        : "r"(a[0]), "r"(a[1]), "r"(a[2]), "r"(a[3]), "r"(b[0]), "r"(b[1]));
}
__device__ __forceinline__ uint32_t smem_to_u32(const void* p) {
    uint32_t a;
    asm("{ .reg .u64 t; cvta.to.shared.u64 t, %1; cvt.u32.u64 %0, t; }"
        : "=r"(a) : "l"(p));
    return a;
}
__device__ __forceinline__ void cp_async16(uint32_t dst, const void* src) {
    asm volatile("cp.async.cg.shared.global [%0], [%1], 16;"
                 :: "r"(dst), "l"(src));
}
__device__ __forceinline__ void cp_commit() {
    asm volatile("cp.async.commit_group;");
}
template <int N>
__device__ __forceinline__ void cp_wait() {
    asm volatile("cp.async.wait_group %0;" :: "n"(N));
}

// ---------------- prep ----------------
// One pass over x: fp16 direct plane + per-batch transposed fp16 plane +
// rowsum zero-fill. block (32,8), grid (HID/32, SEQ/32, BATCH).
__global__ __launch_bounds__(256) void fused_prep(
    const float* __restrict__ x, __half* __restrict__ xf,
    __half* __restrict__ xT, float* __restrict__ rowsum)
{
    __shared__ float t[32][33];
    const size_t base = (size_t)blockIdx.z * SEQ * HID;
    const int c0 = blockIdx.x * 32;   // hid
    const int r0 = blockIdx.y * 32;   // seq
    const int tx = threadIdx.x, ty = threadIdx.y;

#pragma unroll
    for (int j = 0; j < 4; j++) {
        int r = r0 + ty + j * 8;
        size_t o = base + (size_t)r * HID + c0 + tx;
        float v = x[o];
        t[ty + j * 8][tx] = v;
        xf[o] = __float2half_rn(v);
    }
    if (blockIdx.x == 0 && blockIdx.z == 0)
        rowsum[blockIdx.y * 256 + ty * 32 + tx] = 0.f;
    __syncthreads();
#pragma unroll
    for (int j = 0; j < 4; j++) {
        float v = t[tx][ty + j * 8];             // seq=r0+tx, hid=c0+ty+j*8
        size_t o = base + (size_t)(c0 + ty + j * 8) * SEQ + r0 + tx;
        xT[o] = __float2half_rn(v);
    }
}

// W transpose -> fp16, both weights in one launch (z selects).
__global__ __launch_bounds__(256) void transpose_w(
    const float* __restrict__ Wq, const float* __restrict__ Wk,
    __half* __restrict__ WT)
{
    __shared__ float t[32][33];
    const float* src = blockIdx.z ? Wk : Wq;
    __half* dst = WT + (size_t)blockIdx.z * HID * HID;
    int c0 = blockIdx.x * 32, r0 = blockIdx.y * 32;
    int tx = threadIdx.x, ty = threadIdx.y;
#pragma unroll
    for (int j = 0; j < 4; j++)
        t[ty + j * 8][tx] = src[(size_t)(r0 + ty + j * 8) * HID + c0 + tx];
    __syncthreads();
#pragma unroll
    for (int j = 0; j < 4; j++)
        dst[(size_t)(c0 + ty + j * 8) * HID + r0 + tx] =
            __float2half_rn(t[tx][ty + j * 8]);
}

// ===========================================================================
// fp16 HMMA GEMM: C[M,N] = A[M,K] @ B[N,K]^T, fp32 accum, single combo.
// CTA 128x128, warp tile 64x32 (warp_m=wid&1, warp_n=wid>>1), K-chunk 32,
// 2-stage cp.async. Epilogues:
//   Ch&&!rowsum: (d+bias[z]) -> fp16              (projections)
//   Ch&&rowsum:  exp(d*scale) -> fp16 + rowsum    (scores)
//   Cf:          d / rowsum[row] -> fp32          (out)
// ===========================================================================
#define PLANE_BYTES (128 * 80)            // 10240 (64B payload + 16B pad)
#define STAGE_BYTES (2 * PLANE_BYTES)     // 20480
#define GSMEM_TOTAL (2 * STAGE_BYTES)     // 40960

__global__ __launch_bounds__(256) void gemm_f16(
    const __half* __restrict__ Ap, long long sAb,
    const __half* __restrict__ Bp, long long sBb,
    const float* __restrict__ bias, const float* __restrict__ bias2,
    float scale,
    float* __restrict__ Cf, __half* __restrict__ Ch,
    float* __restrict__ rowsum,
    long long sCb, int N, int K)
{
    extern __shared__ __align__(16) char smem[];

    const int tid = threadIdx.x;
    const int wid = tid >> 5;
    const int lid = tid & 31;
    const int warp_m = wid & 1;
    const int warp_n = wid >> 1;
    const int row0 = blockIdx.y * 128;
    const int col0 = blockIdx.x * 128;
    const int z = blockIdx.z;

    const __half* srcA = Ap + (size_t)z * sAb + (size_t)row0 * K;
    const __half* srcB = Bp + (size_t)z * sBb + (size_t)col0 * K;

    const uint32_t smb = smem_to_u32(smem);
    const int ld_r0 = tid >> 2;
    const int ld_ch = tid & 3;

    const int rA = warp_m * 64 + (lid & 7) + ((lid >> 3) & 1) * 8;
    const uint32_t aoff = (uint32_t)(rA * 80 + ((lid >> 4) & 1) * 16);
    const int rB = warp_n * 32 + (lid & 7) + ((lid >> 4) & 1) * 8;
    const uint32_t boff = (uint32_t)(rB * 80 + ((lid >> 3) & 1) * 16);

    float d[4][4][4];
#pragma unroll
    for (int i = 0; i < 4; i++)
#pragma unroll
        for (int j = 0; j < 4; j++)
#pragma unroll
            for (int c = 0; c < 4; c++) d[i][j][c] = 0.f;

    const int nchunks = K >> 5;

    auto issue = [&](int ci, int st) {
        const int k0 = ci << 5;
        const uint32_t sb = smb + st * STAGE_BYTES;
#pragma unroll
        for (int t = 0; t < 2; t++) {
            int r = ld_r0 + t * 64;
            cp_async16(sb + r * 80 + ld_ch * 16,
                       srcA + (size_t)r * K + k0 + ld_ch * 8);
        }
#pragma unroll
        for (int t = 0; t < 2; t++) {
            int r = ld_r0 + t * 64;
            cp_async16(sb + PLANE_BYTES + r * 80 + ld_ch * 16,
                       srcB + (size_t)r * K + k0 + ld_ch * 8);
        }
        cp_commit();
    };

    issue(0, 0);

    for (int ci = 0; ci < nchunks; ci++) {
        const int st = ci & 1;
        if (ci + 1 < nchunks) {
            issue(ci + 1, st ^ 1);
            cp_wait<1>();
        } else {
            cp_wait<0>();
        }
        __syncthreads();

        const uint32_t sb = smb + st * STAGE_BYTES;
        const uint32_t pA = sb;
        const uint32_t pB = sb + PLANE_BYTES;

#pragma unroll
        for (int ks = 0; ks < 2; ks++) {
            const uint32_t kb = ks * 32;
            uint32_t bh[8];
            ldsm_x4(bh + 0, pB + boff + kb);
            ldsm_x4(bh + 4, pB + boff + kb + 1280);
#pragma unroll
            for (int mi = 0; mi < 4; mi++) {
                uint32_t ah[4];
                ldsm_x4(ah, pA + aoff + kb + mi * 1280);
#pragma unroll
                for (int ni = 0; ni < 4; ni++)
                    mma_f16(d[mi][ni], ah, bh + ni * 2);
            }
        }
        __syncthreads();
    }

    // ---- epilogue ----
    const int tr = lid >> 2;
    const int tc = (lid & 3) * 2;

    if (Cf) {
        // out GEMM: normalize by rowsum
#pragma unroll
        for (int mi = 0; mi < 4; mi++) {
            int r0g = row0 + warp_m * 64 + mi * 16 + tr;
            float inv0 = 1.0f / rowsum[z * SEQ + r0g];
            float inv1 = 1.0f / rowsum[z * SEQ + r0g + 8];
#pragma unroll
            for (int ni = 0; ni < 4; ni++) {
                int cg = col0 + warp_n * 32 + ni * 8 + tc;
                float* dst0 = Cf + (size_t)z * sCb + (size_t)r0g * N + cg;
                float* dst1 = dst0 + (size_t)8 * N;
                *(float2*)dst0 = make_float2(d[mi][ni][0] * inv0, d[mi][ni][1] * inv0);
                *(float2*)dst1 = make_float2(d[mi][ni][2] * inv1, d[mi][ni][3] * inv1);
            }
        }
    } else if (rowsum) {
        // scores: e = exp(d*scale) -> fp16, accumulate row sums
        float rs[4][2];
#pragma unroll
        for (int mi = 0; mi < 4; mi++) { rs[mi][0] = 0.f; rs[mi][1] = 0.f; }
#pragma unroll
        for (int mi = 0; mi < 4; mi++) {
            int r0g = row0 + warp_m * 64 + mi * 16 + tr;
#pragma unroll
            for (int ni = 0; ni < 4; ni++) {
                int cg = col0 + warp_n * 32 + ni * 8 + tc;
                float e0 = __expf(d[mi][ni][0] * scale);
                float e1 = __expf(d[mi][ni][1] * scale);
                float e2 = __expf(d[mi][ni][2] * scale);
                float e3 = __expf(d[mi][ni][3] * scale);
                rs[mi][0] += e0 + e1;
                rs[mi][1] += e2 + e3;
                __half2 p0; p0.x = __float2half_rn(e0); p0.y = __float2half_rn(e1);
                __half2 p1; p1.x = __float2half_rn(e2); p1.y = __float2half_rn(e3);
                size_t o0 = (size_t)z * sCb + (size_t)r0g * N + cg;
                *(__half2*)(Ch + o0) = p0;
                *(__half2*)(Ch + o0 + (size_t)8 * N) = p1;
            }
        }
#pragma unroll
        for (int mi = 0; mi < 4; mi++) {
#pragma unroll
            for (int h = 0; h < 2; h++) {
                float v = rs[mi][h];
                v += __shfl_xor_sync(0xffffffff, v, 1);
                v += __shfl_xor_sync(0xffffffff, v, 2);
                if ((lid & 3) == 0) {
                    int r = row0 + warp_m * 64 + mi * 16 + tr + h * 8;
                    atomicAdd(rowsum + z * SEQ + r, v);
                }
            }
        }
    } else {
        // projection: d + bias[z] -> fp16
        const float* bz = (bias2 && z == 1) ? bias2 : bias;
#pragma unroll
        for (int mi = 0; mi < 4; mi++) {
            int r0g = row0 + warp_m * 64 + mi * 16 + tr;
#pragma unroll
            for (int ni = 0; ni < 4; ni++) {
                int cg = col0 + warp_n * 32 + ni * 8 + tc;
                float b0 = bz[cg], b1 = bz[cg + 1];
#pragma unroll
                for (int half = 0; half < 2; half++) {
                    __half2 p;
                    p.x = __float2half_rn(d[mi][ni][half * 2 + 0] + b0);
                    p.y = __float2half_rn(d[mi][ni][half * 2 + 1] + b1);
                    size_t o = (size_t)z * sCb + (size_t)(r0g + half * 8) * N + cg;
                    *(__half2*)(Ch + o) = p;
                }
            }
        }
    }
}

// ---------------------------------------------------------------------------
extern "C" void kernel_launch(void* const* d_in, const int* in_sizes, int n_in,
                              void* d_out, int out_size)
{
    const float* x  = (const float*)d_in[0];  // [8,2048,512]
    const float* Wq = (const float*)d_in[1];  // [512,512]
    const float* bq = (const float*)d_in[2];  // [512]
    const float* Wk = (const float*)d_in[3];  // [512,512]
    const float* bk = (const float*)d_in[4];  // [512]
    float* out = (float*)d_out;               // [8,2048,512]

    cudaFuncSetAttribute(gemm_f16,
                         cudaFuncAttributeMaxDynamicSharedMemorySize, GSMEM_TOTAL);

    __half *xf, *xT, *WT, *QKf, *Ef;
    float* rowsum;
    cudaGetSymbolAddress((void**)&xf,  g_xf);
    cudaGetSymbolAddress((void**)&xT,  g_xT);
    cudaGetSymbolAddress((void**)&WT,  g_WT);
    cudaGetSymbolAddress((void**)&QKf, g_QKf);
    cudaGetSymbolAddress((void**)&Ef,  g_Ef);
    cudaGetSymbolAddress((void**)&rowsum, g_rowsum);

    const float scaleQ = 1.0f / sqrtf((float)HID);

    // --- prep ---
    {
        dim3 g(HID / 32, SEQ / 32, BATCH);
        dim3 b(32, 8);
        fused_prep<<<g, b>>>(x, xf, xT, rowsum);
    }
    {
        dim3 g(HID / 32, HID / 32, 2);
        dim3 b(32, 8);
        transpose_w<<<g, b>>>(Wq, Wk, WT);
    }

    // --- merged Q/K projections: z=0->Q, z=1->K ---
    {
        dim3 grid(HID / 128, MROWS / 128, 2);
        gemm_f16<<<grid, 256, GSMEM_TOTAL>>>(
            xf, 0, WT, (long long)HID * HID,
            bq, bk, 1.0f,
            nullptr, QKf, nullptr, (long long)MROWS * HID, HID, HID);
    }
    // --- scores+exp: E = exp((Q@K^T)/sqrt(D)) -> fp16 + rowsum ---
    {
        dim3 grid(SEQ / 128, SEQ / 128, BATCH);
        gemm_f16<<<grid, 256, GSMEM_TOTAL>>>(
            QKf, (long long)SEQ * HID,
            QKf + (size_t)MROWS * HID, (long long)SEQ * HID,
            nullptr, nullptr, scaleQ,
            nullptr, Ef, rowsum, (long long)SEQ * SEQ, SEQ, HID);
    }
    // --- out = (E @ xT^T) / rowsum  (per batch 2048x512, K=2048) ---
    {
        dim3 grid(HID / 128, SEQ / 128, BATCH);
        gemm_f16<<<grid, 256, GSMEM_TOTAL>>>(
            Ef, (long long)SEQ * SEQ,
            xT, (long long)HID * SEQ,
            nullptr, nullptr, 1.0f,
            out, nullptr, rowsum, (long long)SEQ * HID, HID, SEQ);
    }
}

// round 12
// speedup vs baseline: 2.8551x; 1.1609x over previous
#include <cuda_runtime.h>
#include <cuda_fp16.h>
#include <cstdint>
#include <math.h>

// ===========================================================================
// SelfAttention, fp16-operand HMMA pipeline (base sm_103 ISA).
// HMMA multiplies fp16 exactly into fp32 accumulators; error = input
// rounding only. R11: K-chunk 64 (half the barriers, double the MMA
// run-length per sync) with 144B smem row stride (conflict-free ldsm).
//   proj:   Q|K = x_f16 @ W_f16^T + b        -> fp16
//   scores: E = exp((Q@K^T)/sqrt(D))         -> fp16 + rowsum
//   out:    out = (E @ xT^T) / rowsum        -> fp32
// ===========================================================================

#define BATCH 8
#define SEQ   2048
#define HID   512
#define MROWS (BATCH * SEQ)   // 16384

// ---------------- scratch (__device__ globals) ----------------
__device__ __half g_xf [MROWS * HID];          // x fp16 (proj A operand)
__device__ __half g_xT [MROWS * HID];          // per-batch [512,2048] fp16
__device__ __half g_WT [2 * HID * HID];        // slot0 WqT, slot1 WkT
__device__ __half g_QKf[2 * (size_t)MROWS * HID];  // slot0 Q, slot1 K
__device__ __half g_Ef [(size_t)BATCH * SEQ * SEQ]; // 67 MB exp(S) fp16
__device__ float  g_rowsum[MROWS];

// ---------------- asm helpers (base ISA) ----------------
__device__ __forceinline__ void ldsm_x4(uint32_t* r, uint32_t addr) {
    asm volatile("ldmatrix.sync.aligned.m8n8.x4.shared.b16 {%0,%1,%2,%3}, [%4];"
                 : "=r"(r[0]), "=r"(r[1]), "=r"(r[2]), "=r"(r[3]) : "r"(addr));
}
__device__ __forceinline__ void mma_f16(float* d, const uint32_t* a, const uint32_t* b) {
    asm volatile(
        "mma.sync.aligned.m16n8k16.row.col.f32.f16.f16.f32 "
        "{%0,%1,%2,%3}, {%4,%5,%6,%7}, {%8,%9}, {%0,%1,%2,%3};"
        : "+f"(d[0]), "+f"(d[1]), "+f"(d[2]), "+f"(d[3])
        : "r"(a[0]), "r"(a[1]), "r"(a[2]), "r"(a[3]), "r"(b[0]), "r"(b[1]));
}
__device__ __forceinline__ uint32_t smem_to_u32(const void* p) {
    uint32_t a;
    asm("{ .reg .u64 t; cvta.to.shared.u64 t, %1; cvt.u32.u64 %0, t; }"
        : "=r"(a) : "l"(p));
    return a;
}
__device__ __forceinline__ void cp_async16(uint32_t dst, const void* src) {
    asm volatile("cp.async.cg.shared.global [%0], [%1], 16;"
                 :: "r"(dst), "l"(src));
}
__device__ __forceinline__ void cp_commit() {
    asm volatile("cp.async.commit_group;");
}
template <int N>
__device__ __forceinline__ void cp_wait() {
    asm volatile("cp.async.wait_group %0;" :: "n"(N));
}

// ---------------- prep ----------------
__global__ __launch_bounds__(256) void fused_prep(
    const float* __restrict__ x, __half* __restrict__ xf,
    __half* __restrict__ xT, float* __restrict__ rowsum)
{
    __shared__ float t[32][33];
    const size_t base = (size_t)blockIdx.z * SEQ * HID;
    const int c0 = blockIdx.x * 32;   // hid
    const int r0 = blockIdx.y * 32;   // seq
    const int tx = threadIdx.x, ty = threadIdx.y;

#pragma unroll
    for (int j = 0; j < 4; j++) {
        int r = r0 + ty + j * 8;
        size_t o = base + (size_t)r * HID + c0 + tx;
        float v = x[o];
        t[ty + j * 8][tx] = v;
        xf[o] = __float2half_rn(v);
    }
    if (blockIdx.x == 0 && blockIdx.z == 0)
        rowsum[blockIdx.y * 256 + ty * 32 + tx] = 0.f;
    __syncthreads();
#pragma unroll
    for (int j = 0; j < 4; j++) {
        float v = t[tx][ty + j * 8];             // seq=r0+tx, hid=c0+ty+j*8
        size_t o = base + (size_t)(c0 + ty + j * 8) * SEQ + r0 + tx;
        xT[o] = __float2half_rn(v);
    }
}

__global__ __launch_bounds__(256) void transpose_w(
    const float* __restrict__ Wq, const float* __restrict__ Wk,
    __half* __restrict__ WT)
{
    __shared__ float t[32][33];
    const float* src = blockIdx.z ? Wk : Wq;
    __half* dst = WT + (size_t)blockIdx.z * HID * HID;
    int c0 = blockIdx.x * 32, r0 = blockIdx.y * 32;
    int tx = threadIdx.x, ty = threadIdx.y;
#pragma unroll
    for (int j = 0; j < 4; j++)
        t[ty + j * 8][tx] = src[(size_t)(r0 + ty + j * 8) * HID + c0 + tx];
    __syncthreads();
#pragma unroll
    for (int j = 0; j < 4; j++)
        dst[(size_t)(c0 + ty + j * 8) * HID + r0 + tx] =
            __float2half_rn(t[tx][ty + j * 8]);
}

// ===========================================================================
// fp16 HMMA GEMM: C[M,N] = A[M,K] @ B[N,K]^T, fp32 accum, single combo.
// CTA 128x128, warp tile 64x32 (warp_m=wid&1, warp_n=wid>>1), K-chunk 64,
// 2-stage cp.async. smem rows: 128B payload + 16B pad (stride 144 — the
// stride is 4 banks mod 32, so 8-row ldsm gathers are conflict-free).
// Epilogues: Ch&&!rowsum: (d+bias[z]) -> fp16       (projections)
//            Ch&&rowsum:  exp(d*scale)->fp16+rowsum (scores)
//            Cf:          d / rowsum[row] -> fp32   (out)
// ===========================================================================
#define ROW_BYTES   144
#define PLANE_BYTES (128 * ROW_BYTES)     // 18432
#define STAGE_BYTES (2 * PLANE_BYTES)     // 36864
#define GSMEM_TOTAL (2 * STAGE_BYTES)     // 73728

__global__ __launch_bounds__(256) void gemm_f16(
    const __half* __restrict__ Ap, long long sAb,
    const __half* __restrict__ Bp, long long sBb,
    const float* __restrict__ bias, const float* __restrict__ bias2,
    float scale,
    float* __restrict__ Cf, __half* __restrict__ Ch,
    float* __restrict__ rowsum,
    long long sCb, int N, int K)
{
    extern __shared__ __align__(16) char smem[];

    const int tid = threadIdx.x;
    const int wid = tid >> 5;
    const int lid = tid & 31;
    const int warp_m = wid & 1;
    const int warp_n = wid >> 1;
    const int row0 = blockIdx.y * 128;
    const int col0 = blockIdx.x * 128;
    const int z = blockIdx.z;

    const __half* srcA = Ap + (size_t)z * sAb + (size_t)row0 * K;
    const __half* srcB = Bp + (size_t)z * sBb + (size_t)col0 * K;

    const uint32_t smb = smem_to_u32(smem);
    // cp.async mapping: 128 rows x 8 chunks of 16B per plane; 1024 per plane
    const int ld_r = tid >> 3;        // 0..31 (x4 passes of 32 rows)
    const int ld_ch = tid & 7;        // 16B chunk in 128B payload

    const int rA = warp_m * 64 + (lid & 15);
    const uint32_t aoff = (uint32_t)(rA * ROW_BYTES + ((lid >> 4) & 1) * 16);
    const int rB = warp_n * 32 + (lid & 7) + ((lid >> 4) & 1) * 8;
    const uint32_t boff = (uint32_t)(rB * ROW_BYTES + ((lid >> 3) & 1) * 16);

    float d[4][4][4];
#pragma unroll
    for (int i = 0; i < 4; i++)
#pragma unroll
        for (int j = 0; j < 4; j++)
#pragma unroll
            for (int c = 0; c < 4; c++) d[i][j][c] = 0.f;

    const int nchunks = K >> 6;

    auto issue = [&](int ci, int st) {
        const int k0 = ci << 6;
        const uint32_t sb = smb + st * STAGE_BYTES;
#pragma unroll
        for (int t = 0; t < 4; t++) {
            int r = ld_r + t * 32;
            cp_async16(sb + r * ROW_BYTES + ld_ch * 16,
                       srcA + (size_t)r * K + k0 + ld_ch * 8);
        }
#pragma unroll
        for (int t = 0; t < 4; t++) {
            int r = ld_r + t * 32;
            cp_async16(sb + PLANE_BYTES + r * ROW_BYTES + ld_ch * 16,
                       srcB + (size_t)r * K + k0 + ld_ch * 8);
        }
        cp_commit();
    };

    issue(0, 0);

    for (int ci = 0; ci < nchunks; ci++) {
        const int st = ci & 1;
        if (ci + 1 < nchunks) {
            issue(ci + 1, st ^ 1);
            cp_wait<1>();
        } else {
            cp_wait<0>();
        }
        __syncthreads();

        const uint32_t sb = smb + st * STAGE_BYTES;
        const uint32_t pA = sb;
        const uint32_t pB = sb + PLANE_BYTES;

#pragma unroll
        for (int ks = 0; ks < 4; ks++) {
            const uint32_t kb = ks * 32;          // 16 halves = 32B per k-step
            uint32_t bh[8];
            ldsm_x4(bh + 0, pB + boff + kb);
            ldsm_x4(bh + 4, pB + boff + kb + 16 * ROW_BYTES);
#pragma unroll
            for (int mi = 0; mi < 4; mi++) {
                uint32_t ah[4];
                ldsm_x4(ah, pA + aoff + kb + mi * 16 * ROW_BYTES);
#pragma unroll
                for (int ni = 0; ni < 4; ni++)
                    mma_f16(d[mi][ni], ah, bh + ni * 2);
            }
        }
        __syncthreads();
    }

    // ---- epilogue ----
    const int tr = lid >> 2;
    const int tc = (lid & 3) * 2;

    if (Cf) {
        // out GEMM: normalize by rowsum
#pragma unroll
        for (int mi = 0; mi < 4; mi++) {
            int r0g = row0 + warp_m * 64 + mi * 16 + tr;
            float inv0 = 1.0f / rowsum[z * SEQ + r0g];
            float inv1 = 1.0f / rowsum[z * SEQ + r0g + 8];
#pragma unroll
            for (int ni = 0; ni < 4; ni++) {
                int cg = col0 + warp_n * 32 + ni * 8 + tc;
                float* dst0 = Cf + (size_t)z * sCb + (size_t)r0g * N + cg;
                float* dst1 = dst0 + (size_t)8 * N;
                *(float2*)dst0 = make_float2(d[mi][ni][0] * inv0, d[mi][ni][1] * inv0);
                *(float2*)dst1 = make_float2(d[mi][ni][2] * inv1, d[mi][ni][3] * inv1);
            }
        }
    } else if (rowsum) {
        // scores: e = exp(d*scale) -> fp16, accumulate row sums
        float rs[4][2];
#pragma unroll
        for (int mi = 0; mi < 4; mi++) { rs[mi][0] = 0.f; rs[mi][1] = 0.f; }
#pragma unroll
        for (int mi = 0; mi < 4; mi++) {
            int r0g = row0 + warp_m * 64 + mi * 16 + tr;
#pragma unroll
            for (int ni = 0; ni < 4; ni++) {
                int cg = col0 + warp_n * 32 + ni * 8 + tc;
                float e0 = __expf(d[mi][ni][0] * scale);
                float e1 = __expf(d[mi][ni][1] * scale);
                float e2 = __expf(d[mi][ni][2] * scale);
                float e3 = __expf(d[mi][ni][3] * scale);
                rs[mi][0] += e0 + e1;
                rs[mi][1] += e2 + e3;
                __half2 p0; p0.x = __float2half_rn(e0); p0.y = __float2half_rn(e1);
                __half2 p1; p1.x = __float2half_rn(e2); p1.y = __float2half_rn(e3);
                size_t o0 = (size_t)z * sCb + (size_t)r0g * N + cg;
                *(__half2*)(Ch + o0) = p0;
                *(__half2*)(Ch + o0 + (size_t)8 * N) = p1;
            }
        }
#pragma unroll
        for (int mi = 0; mi < 4; mi++) {
#pragma unroll
            for (int h = 0; h < 2; h++) {
                float v = rs[mi][h];
                v += __shfl_xor_sync(0xffffffff, v, 1);
                v += __shfl_xor_sync(0xffffffff, v, 2);
                if ((lid & 3) == 0) {
                    int r = row0 + warp_m * 64 + mi * 16 + tr + h * 8;
                    atomicAdd(rowsum + z * SEQ + r, v);
                }
            }
        }
    } else {
        // projection: d + bias[z] -> fp16
        const float* bz = (bias2 && z == 1) ? bias2 : bias;
#pragma unroll
        for (int mi = 0; mi < 4; mi++) {
            int r0g = row0 + warp_m * 64 + mi * 16 + tr;
#pragma unroll
            for (int ni = 0; ni < 4; ni++) {
                int cg = col0 + warp_n * 32 + ni * 8 + tc;
                float b0 = bz[cg], b1 = bz[cg + 1];
#pragma unroll
                for (int half = 0; half < 2; half++) {
                    __half2 p;
                    p.x = __float2half_rn(d[mi][ni][half * 2 + 0] + b0);
                    p.y = __float2half_rn(d[mi][ni][half * 2 + 1] + b1);
                    size_t o = (size_t)z * sCb + (size_t)(r0g + half * 8) * N + cg;
                    *(__half2*)(Ch + o) = p;
                }
            }
        }
    }
}

// ---------------------------------------------------------------------------
extern "C" void kernel_launch(void* const* d_in, const int* in_sizes, int n_in,
                              void* d_out, int out_size)
{
    const float* x  = (const float*)d_in[0];  // [8,2048,512]
    const float* Wq = (const float*)d_in[1];  // [512,512]
    const float* bq = (const float*)d_in[2];  // [512]
    const float* Wk = (const float*)d_in[3];  // [512,512]
    const float* bk = (const float*)d_in[4];  // [512]
    float* out = (float*)d_out;               // [8,2048,512]

    cudaFuncSetAttribute(gemm_f16,
                         cudaFuncAttributeMaxDynamicSharedMemorySize, GSMEM_TOTAL);

    __half *xf, *xT, *WT, *QKf, *Ef;
    float* rowsum;
    cudaGetSymbolAddress((void**)&xf,  g_xf);
    cudaGetSymbolAddress((void**)&xT,  g_xT);
    cudaGetSymbolAddress((void**)&WT,  g_WT);
    cudaGetSymbolAddress((void**)&QKf, g_QKf);
    cudaGetSymbolAddress((void**)&Ef,  g_Ef);
    cudaGetSymbolAddress((void**)&rowsum, g_rowsum);

    const float scaleQ = 1.0f / sqrtf((float)HID);

    // --- prep ---
    {
        dim3 g(HID / 32, SEQ / 32, BATCH);
        dim3 b(32, 8);
        fused_prep<<<g, b>>>(x, xf, xT, rowsum);
    }
    {
        dim3 g(HID / 32, HID / 32, 2);
        dim3 b(32, 8);
        transpose_w<<<g, b>>>(Wq, Wk, WT);
    }

    // --- merged Q/K projections: z=0->Q, z=1->K ---
    {
        dim3 grid(HID / 128, MROWS / 128, 2);
        gemm_f16<<<grid, 256, GSMEM_TOTAL>>>(
            xf, 0, WT, (long long)HID * HID,
            bq, bk, 1.0f,
            nullptr, QKf, nullptr, (long long)MROWS * HID, HID, HID);
    }
    // --- scores+exp: E = exp((Q@K^T)/sqrt(D)) -> fp16 + rowsum ---
    {
        dim3 grid(SEQ / 128, SEQ / 128, BATCH);
        gemm_f16<<<grid, 256, GSMEM_TOTAL>>>(
            QKf, (long long)SEQ * HID,
            QKf + (size_t)MROWS * HID, (long long)SEQ * HID,
            nullptr, nullptr, scaleQ,
            nullptr, Ef, rowsum, (long long)SEQ * SEQ, SEQ, HID);
    }
    // --- out = (E @ xT^T) / rowsum  (per batch 2048x512, K=2048) ---
    {
        dim3 grid(HID / 128, SEQ / 128, BATCH);
        gemm_f16<<<grid, 256, GSMEM_TOTAL>>>(
            Ef, (long long)SEQ * SEQ,
            xT, (long long)HID * SEQ,
            nullptr, nullptr, 1.0f,
            out, nullptr, rowsum, (long long)SEQ * HID, HID, SEQ);
    }
}

// round 13
// speedup vs baseline: 3.1500x; 1.1033x over previous
#include <cuda_runtime.h>
#include <cuda_fp16.h>
#include <cstdint>
#include <math.h>

// ===========================================================================
// SelfAttention, fp16-operand HMMA pipeline (base sm_103 ISA).
// R12: mbarrier-based 3-stage async pipeline in the GEMM mainloop —
// no cp.async.wait_group, no __syncthreads re-phasing. Producers signal
// per-stage `full` barriers via cp.async.mbarrier.arrive.noinc (256 thread
// arrives); consumers signal `empty` via one arrive per warp (8).
//   proj:   Q|K = x_f16 @ W_f16^T + b        -> fp16
//   scores: E = exp((Q@K^T)/sqrt(D))         -> fp16 + rowsum
//   out:    out = (E @ xT^T) / rowsum        -> fp32
// ===========================================================================

#define BATCH 8
#define SEQ   2048
#define HID   512
#define MROWS (BATCH * SEQ)   // 16384

// ---------------- scratch (__device__ globals) ----------------
__device__ __half g_xf [MROWS * HID];
__device__ __half g_xT [MROWS * HID];          // per-batch [512,2048]
__device__ __half g_WT [2 * HID * HID];        // slot0 WqT, slot1 WkT
__device__ __half g_QKf[2 * (size_t)MROWS * HID];  // slot0 Q, slot1 K
__device__ __half g_Ef [(size_t)BATCH * SEQ * SEQ]; // 67 MB exp(S)
__device__ float  g_rowsum[MROWS];

// ---------------- asm helpers (base ISA) ----------------
__device__ __forceinline__ void ldsm_x4(uint32_t* r, uint32_t addr) {
    asm volatile("ldmatrix.sync.aligned.m8n8.x4.shared.b16 {%0,%1,%2,%3}, [%4];"
                 : "=r"(r[0]), "=r"(r[1]), "=r"(r[2]), "=r"(r[3]) : "r"(addr));
}
__device__ __forceinline__ void mma_f16(float* d, const uint32_t* a, const uint32_t* b) {
    asm volatile(
        "mma.sync.aligned.m16n8k16.row.col.f32.f16.f16.f32 "
        "{%0,%1,%2,%3}, {%4,%5,%6,%7}, {%8,%9}, {%0,%1,%2,%3};"
        : "+f"(d[0]), "+f"(d[1]), "+f"(d[2]), "+f"(d[3])
        : "r"(a[0]), "r"(a[1]), "r"(a[2]), "r"(a[3]), "r"(b[0]), "r"(b[1]));
}
__device__ __forceinline__ uint32_t smem_to_u32(const void* p) {
    uint32_t a;
    asm("{ .reg .u64 t; cvta.to.shared.u64 t, %1; cvt.u32.u64 %0, t; }"
        : "=r"(a) : "l"(p));
    return a;
}
__device__ __forceinline__ void cp_async16(uint32_t dst, const void* src) {
    asm volatile("cp.async.cg.shared.global [%0], [%1], 16;"
                 :: "r"(dst), "l"(src));
}
__device__ __forceinline__ void cp_async_mbar_arrive(uint32_t mbar) {
    asm volatile("cp.async.mbarrier.arrive.noinc.shared::cta.b64 [%0];"
                 :: "r"(mbar) : "memory");
}
#define MBARRIER_INIT(mbar, cnt) \
    asm volatile("mbarrier.init.shared.b64 [%0], %1;" \
                 :: "r"((uint32_t)(mbar)), "r"((uint32_t)(cnt)) : "memory")
#define MBARRIER_ARRIVE(mbar) \
    asm volatile("mbarrier.arrive.shared.b64 _, [%0];" \
                 :: "r"((uint32_t)(mbar)) : "memory")
#define MBARRIER_WAIT_PARITY(mbar, parity) do {                              \
    uint32_t _m = (uint32_t)(mbar); uint32_t _p = (uint32_t)(parity);        \
    uint32_t _done;                                                          \
    asm volatile(                                                            \
        "{\n\t.reg .pred p;\n\t"                                             \
        "mbarrier.try_wait.parity.acquire.cta.shared::cta.b64 p, [%1], %2;\n\t" \
        "selp.b32 %0, 1, 0, p;\n\t}"                                         \
        : "=r"(_done) : "r"(_m), "r"(_p) : "memory");                        \
    if (!_done) {                                                            \
        asm volatile(                                                        \
            "{\n\t.reg .pred P1;\n\t"                                        \
            "WAIT_LOOP_%=:\n\t"                                              \
            "mbarrier.try_wait.parity.acquire.cta.shared::cta.b64 P1, [%0], %1, 0x989680;\n\t" \
            "@P1 bra.uni WAIT_DONE_%=;\n\t"                                  \
            "bra.uni WAIT_LOOP_%=;\n\t"                                      \
            "WAIT_DONE_%=:\n\t}"                                             \
            :: "r"(_m), "r"(_p) : "memory");                                 \
    }                                                                        \
} while (0)

// ---------------- prep ----------------
__global__ __launch_bounds__(256) void fused_prep(
    const float* __restrict__ x, __half* __restrict__ xf,
    __half* __restrict__ xT, float* __restrict__ rowsum)
{
    __shared__ float t[32][33];
    const size_t base = (size_t)blockIdx.z * SEQ * HID;
    const int c0 = blockIdx.x * 32;   // hid
    const int r0 = blockIdx.y * 32;   // seq
    const int tx = threadIdx.x, ty = threadIdx.y;

#pragma unroll
    for (int j = 0; j < 4; j++) {
        int r = r0 + ty + j * 8;
        size_t o = base + (size_t)r * HID + c0 + tx;
        float v = x[o];
        t[ty + j * 8][tx] = v;
        xf[o] = __float2half_rn(v);
    }
    if (blockIdx.x == 0 && blockIdx.z == 0)
        rowsum[blockIdx.y * 256 + ty * 32 + tx] = 0.f;
    __syncthreads();
#pragma unroll
    for (int j = 0; j < 4; j++) {
        float v = t[tx][ty + j * 8];
        size_t o = base + (size_t)(c0 + ty + j * 8) * SEQ + r0 + tx;
        xT[o] = __float2half_rn(v);
    }
}

__global__ __launch_bounds__(256) void transpose_w(
    const float* __restrict__ Wq, const float* __restrict__ Wk,
    __half* __restrict__ WT)
{
    __shared__ float t[32][33];
    const float* src = blockIdx.z ? Wk : Wq;
    __half* dst = WT + (size_t)blockIdx.z * HID * HID;
    int c0 = blockIdx.x * 32, r0 = blockIdx.y * 32;
    int tx = threadIdx.x, ty = threadIdx.y;
#pragma unroll
    for (int j = 0; j < 4; j++)
        t[ty + j * 8][tx] = src[(size_t)(r0 + ty + j * 8) * HID + c0 + tx];
    __syncthreads();
#pragma unroll
    for (int j = 0; j < 4; j++)
        dst[(size_t)(c0 + ty + j * 8) * HID + r0 + tx] =
            __float2half_rn(t[tx][ty + j * 8]);
}

// ===========================================================================
// fp16 HMMA GEMM, mbarrier 3-stage pipeline.
// CTA 128x128, warp tile 64x32, K-chunk 64, smem row stride 144B.
// Stage s barriers: full[s] (count 256, cp.async.noinc arrives),
//                   empty[s] (count 8, one arrive per warp).
// ===========================================================================
#define ROW_BYTES   144
#define PLANE_BYTES (128 * ROW_BYTES)     // 18432
#define STAGE_BYTES (2 * PLANE_BYTES)     // 36864
#define NSTAGES     3
#define MBAR_AREA   128
#define GSMEM_TOTAL (MBAR_AREA + NSTAGES * STAGE_BYTES)   // 110720

__global__ __launch_bounds__(256, 2) void gemm_f16(
    const __half* __restrict__ Ap, long long sAb,
    const __half* __restrict__ Bp, long long sBb,
    const float* __restrict__ bias, const float* __restrict__ bias2,
    float scale,
    float* __restrict__ Cf, __half* __restrict__ Ch,
    float* __restrict__ rowsum,
    long long sCb, int N, int K)
{
    extern __shared__ __align__(16) char smem[];

    const int tid = threadIdx.x;
    const int wid = tid >> 5;
    const int lid = tid & 31;
    const int warp_m = wid & 1;
    const int warp_n = wid >> 1;
    const int row0 = blockIdx.y * 128;
    const int col0 = blockIdx.x * 128;
    const int z = blockIdx.z;

    const __half* srcA = Ap + (size_t)z * sAb + (size_t)row0 * K;
    const __half* srcB = Bp + (size_t)z * sBb + (size_t)col0 * K;

    const uint32_t smb = smem_to_u32(smem);
    const uint32_t tiles = smb + MBAR_AREA;

    // barriers: full[s] at smb + s*16, empty[s] at smb + s*16 + 8
    if (tid == 0) {
#pragma unroll
        for (int s = 0; s < NSTAGES; s++) {
            MBARRIER_INIT(smb + s * 16, 256);
            MBARRIER_INIT(smb + s * 16 + 8, 8);
        }
    }
    __syncthreads();

    const int ld_r = tid >> 3;        // 0..31
    const int ld_ch = tid & 7;        // 16B chunk in 128B payload

    const int rA = warp_m * 64 + (lid & 15);
    const uint32_t aoff = (uint32_t)(rA * ROW_BYTES + ((lid >> 4) & 1) * 16);
    const int rB = warp_n * 32 + (lid & 7) + ((lid >> 4) & 1) * 8;
    const uint32_t boff = (uint32_t)(rB * ROW_BYTES + ((lid >> 3) & 1) * 16);

    float d[4][4][4];
#pragma unroll
    for (int i = 0; i < 4; i++)
#pragma unroll
        for (int j = 0; j < 4; j++)
#pragma unroll
            for (int c = 0; c < 4; c++) d[i][j][c] = 0.f;

    const int nchunks = K >> 6;

    auto issue = [&](int ci, int st) {
        const int k0 = ci << 6;
        const uint32_t sb = tiles + st * STAGE_BYTES;
#pragma unroll
        for (int t = 0; t < 4; t++) {
            int r = ld_r + t * 32;
            cp_async16(sb + r * ROW_BYTES + ld_ch * 16,
                       srcA + (size_t)r * K + k0 + ld_ch * 8);
        }
#pragma unroll
        for (int t = 0; t < 4; t++) {
            int r = ld_r + t * 32;
            cp_async16(sb + PLANE_BYTES + r * ROW_BYTES + ld_ch * 16,
                       srcB + (size_t)r * K + k0 + ld_ch * 8);
        }
        cp_async_mbar_arrive(smb + st * 16);   // full[st], noinc
    };

    // producer cursor (phase 1: first empty-wait on fresh barrier passes),
    // consumer cursor (phase 0)
    int p_st = 0, p_ph = 1;
    int c_st = 0, c_ph = 0;

    // prologue: fill stages 0,1 with chunks 0,1
#pragma unroll
    for (int s = 0; s < 2; s++) {
        MBARRIER_WAIT_PARITY(smb + p_st * 16 + 8, p_ph);   // passes immediately
        issue(s, p_st);
        if (++p_st == NSTAGES) { p_st = 0; p_ph ^= 1; }
    }

    for (int ci = 0; ci < nchunks; ci++) {
        // producer: issue chunk ci+2 into the stage freed by chunk ci-1
        const int nx = ci + 2;
        if (nx < nchunks) {
            MBARRIER_WAIT_PARITY(smb + p_st * 16 + 8, p_ph);
            issue(nx, p_st);
            if (++p_st == NSTAGES) { p_st = 0; p_ph ^= 1; }
        }

        // consumer: wait chunk ci full, compute
        MBARRIER_WAIT_PARITY(smb + c_st * 16, c_ph);

        const uint32_t sb = tiles + c_st * STAGE_BYTES;
        const uint32_t pA = sb;
        const uint32_t pB = sb + PLANE_BYTES;

#pragma unroll
        for (int ks = 0; ks < 4; ks++) {
            const uint32_t kb = ks * 32;
            uint32_t bh[8];
            ldsm_x4(bh + 0, pB + boff + kb);
            ldsm_x4(bh + 4, pB + boff + kb + 16 * ROW_BYTES);
#pragma unroll
            for (int mi = 0; mi < 4; mi++) {
                uint32_t ah[4];
                ldsm_x4(ah, pA + aoff + kb + mi * 16 * ROW_BYTES);
#pragma unroll
                for (int ni = 0; ni < 4; ni++)
                    mma_f16(d[mi][ni], ah, bh + ni * 2);
            }
        }

        __syncwarp();
        if (lid == 0) MBARRIER_ARRIVE(smb + c_st * 16 + 8);   // empty[c_st]
        if (++c_st == NSTAGES) { c_st = 0; c_ph ^= 1; }
    }

    // ---- epilogue ----
    const int tr = lid >> 2;
    const int tc = (lid & 3) * 2;

    if (Cf) {
        // out GEMM: normalize by rowsum
#pragma unroll
        for (int mi = 0; mi < 4; mi++) {
            int r0g = row0 + warp_m * 64 + mi * 16 + tr;
            float inv0 = 1.0f / rowsum[z * SEQ + r0g];
            float inv1 = 1.0f / rowsum[z * SEQ + r0g + 8];
#pragma unroll
            for (int ni = 0; ni < 4; ni++) {
                int cg = col0 + warp_n * 32 + ni * 8 + tc;
                float* dst0 = Cf + (size_t)z * sCb + (size_t)r0g * N + cg;
                float* dst1 = dst0 + (size_t)8 * N;
                *(float2*)dst0 = make_float2(d[mi][ni][0] * inv0, d[mi][ni][1] * inv0);
                *(float2*)dst1 = make_float2(d[mi][ni][2] * inv1, d[mi][ni][3] * inv1);
            }
        }
    } else if (rowsum) {
        // scores: e = exp(d*scale) -> fp16, accumulate row sums
        float rs[4][2];
#pragma unroll
        for (int mi = 0; mi < 4; mi++) { rs[mi][0] = 0.f; rs[mi][1] = 0.f; }
#pragma unroll
        for (int mi = 0; mi < 4; mi++) {
            int r0g = row0 + warp_m * 64 + mi * 16 + tr;
#pragma unroll
            for (int ni = 0; ni < 4; ni++) {
                int cg = col0 + warp_n * 32 + ni * 8 + tc;
                float e0 = __expf(d[mi][ni][0] * scale);
                float e1 = __expf(d[mi][ni][1] * scale);
                float e2 = __expf(d[mi][ni][2] * scale);
                float e3 = __expf(d[mi][ni][3] * scale);
                rs[mi][0] += e0 + e1;
                rs[mi][1] += e2 + e3;
                __half2 p0; p0.x = __float2half_rn(e0); p0.y = __float2half_rn(e1);
                __half2 p1; p1.x = __float2half_rn(e2); p1.y = __float2half_rn(e3);
                size_t o0 = (size_t)z * sCb + (size_t)r0g * N + cg;
                *(__half2*)(Ch + o0) = p0;
                *(__half2*)(Ch + o0 + (size_t)8 * N) = p1;
            }
        }
#pragma unroll
        for (int mi = 0; mi < 4; mi++) {
#pragma unroll
            for (int h = 0; h < 2; h++) {
                float v = rs[mi][h];
                v += __shfl_xor_sync(0xffffffff, v, 1);
                v += __shfl_xor_sync(0xffffffff, v, 2);
                if ((lid & 3) == 0) {
                    int r = row0 + warp_m * 64 + mi * 16 + tr + h * 8;
                    atomicAdd(rowsum + z * SEQ + r, v);
                }
            }
        }
    } else {
        // projection: d + bias[z] -> fp16
        const float* bz = (bias2 && z == 1) ? bias2 : bias;
#pragma unroll
        for (int mi = 0; mi < 4; mi++) {
            int r0g = row0 + warp_m * 64 + mi * 16 + tr;
#pragma unroll
            for (int ni = 0; ni < 4; ni++) {
                int cg = col0 + warp_n * 32 + ni * 8 + tc;
                float b0 = bz[cg], b1 = bz[cg + 1];
#pragma unroll
                for (int half = 0; half < 2; half++) {
                    __half2 p;
                    p.x = __float2half_rn(d[mi][ni][half * 2 + 0] + b0);
                    p.y = __float2half_rn(d[mi][ni][half * 2 + 1] + b1);
                    size_t o = (size_t)z * sCb + (size_t)(r0g + half * 8) * N + cg;
                    *(__half2*)(Ch + o) = p;
                }
            }
        }
    }
}

// ---------------------------------------------------------------------------
extern "C" void kernel_launch(void* const* d_in, const int* in_sizes, int n_in,
                              void* d_out, int out_size)
{
    const float* x  = (const float*)d_in[0];  // [8,2048,512]
    const float* Wq = (const float*)d_in[1];  // [512,512]
    const float* bq = (const float*)d_in[2];  // [512]
    const float* Wk = (const float*)d_in[3];  // [512,512]
    const float* bk = (const float*)d_in[4];  // [512]
    float* out = (float*)d_out;               // [8,2048,512]

    cudaFuncSetAttribute(gemm_f16,
                         cudaFuncAttributeMaxDynamicSharedMemorySize, GSMEM_TOTAL);

    __half *xf, *xT, *WT, *QKf, *Ef;
    float* rowsum;
    cudaGetSymbolAddress((void**)&xf,  g_xf);
    cudaGetSymbolAddress((void**)&xT,  g_xT);
    cudaGetSymbolAddress((void**)&WT,  g_WT);
    cudaGetSymbolAddress((void**)&QKf, g_QKf);
    cudaGetSymbolAddress((void**)&Ef,  g_Ef);
    cudaGetSymbolAddress((void**)&rowsum, g_rowsum);

    const float scaleQ = 1.0f / sqrtf((float)HID);

    // --- prep ---
    {
        dim3 g(HID / 32, SEQ / 32, BATCH);
        dim3 b(32, 8);
        fused_prep<<<g, b>>>(x, xf, xT, rowsum);
    }
    {
        dim3 g(HID / 32, HID / 32, 2);
        dim3 b(32, 8);
        transpose_w<<<g, b>>>(Wq, Wk, WT);
    }

    // --- merged Q/K projections: z=0->Q, z=1->K ---
    {
        dim3 grid(HID / 128, MROWS / 128, 2);
        gemm_f16<<<grid, 256, GSMEM_TOTAL>>>(
            xf, 0, WT, (long long)HID * HID,
            bq, bk, 1.0f,
            nullptr, QKf, nullptr, (long long)MROWS * HID, HID, HID);
    }
    // --- scores+exp: E = exp((Q@K^T)/sqrt(D)) -> fp16 + rowsum ---
    {
        dim3 grid(SEQ / 128, SEQ / 128, BATCH);
        gemm_f16<<<grid, 256, GSMEM_TOTAL>>>(
            QKf, (long long)SEQ * HID,
            QKf + (size_t)MROWS * HID, (long long)SEQ * HID,
            nullptr, nullptr, scaleQ,
            nullptr, Ef, rowsum, (long long)SEQ * SEQ, SEQ, HID);
    }
    // --- out = (E @ xT^T) / rowsum  (per batch 2048x512, K=2048) ---
    {
        dim3 grid(HID / 128, SEQ / 128, BATCH);
        gemm_f16<<<grid, 256, GSMEM_TOTAL>>>(
            Ef, (long long)SEQ * SEQ,
            xT, (long long)HID * SEQ,
            nullptr, nullptr, 1.0f,
            out, nullptr, rowsum, (long long)SEQ * HID, HID, SEQ);
    }
}

// round 14
// speedup vs baseline: 3.2677x; 1.0374x over previous
#include <cuda_runtime.h>
#include <cuda_fp16.h>
#include <cstdint>
#include <math.h>

// ===========================================================================
// SelfAttention, fp16-operand HMMA pipeline (base sm_103 ISA).
// R13: 64x64 warp tiles on 128-thread CTAs (4 warps, 2x2) — halves ldsm
// bytes/FLOP (smem crossbar was capping tensor at ~61%). 3-stage mbarrier
// pipeline, K-chunk 64, smem row stride 144B.
//   proj:   Q|K = x_f16 @ W_f16^T + b        -> fp16
//   scores: E = exp((Q@K^T)/sqrt(D))         -> fp16 + rowsum
//   out:    out = (E @ xT^T) / rowsum        -> fp32
// ===========================================================================

#define BATCH 8
#define SEQ   2048
#define HID   512
#define MROWS (BATCH * SEQ)   // 16384

// ---------------- scratch (__device__ globals) ----------------
__device__ __half g_xf [MROWS * HID];
__device__ __half g_xT [MROWS * HID];          // per-batch [512,2048]
__device__ __half g_WT [2 * HID * HID];        // slot0 WqT, slot1 WkT
__device__ __half g_QKf[2 * (size_t)MROWS * HID];  // slot0 Q, slot1 K
__device__ __half g_Ef [(size_t)BATCH * SEQ * SEQ]; // 67 MB exp(S)
__device__ float  g_rowsum[MROWS];

// ---------------- asm helpers (base ISA) ----------------
__device__ __forceinline__ void ldsm_x4(uint32_t* r, uint32_t addr) {
    asm volatile("ldmatrix.sync.aligned.m8n8.x4.shared.b16 {%0,%1,%2,%3}, [%4];"
                 : "=r"(r[0]), "=r"(r[1]), "=r"(r[2]), "=r"(r[3]) : "r"(addr));
}
__device__ __forceinline__ void mma_f16(float* d, const uint32_t* a, const uint32_t* b) {
    asm volatile(
        "mma.sync.aligned.m16n8k16.row.col.f32.f16.f16.f32 "
        "{%0,%1,%2,%3}, {%4,%5,%6,%7}, {%8,%9}, {%0,%1,%2,%3};"
        : "+f"(d[0]), "+f"(d[1]), "+f"(d[2]), "+f"(d[3])
        : "r"(a[0]), "r"(a[1]), "r"(a[2]), "r"(a[3]), "r"(b[0]), "r"(b[1]));
}
__device__ __forceinline__ uint32_t smem_to_u32(const void* p) {
    uint32_t a;
    asm("{ .reg .u64 t; cvta.to.shared.u64 t, %1; cvt.u32.u64 %0, t; }"
        : "=r"(a) : "l"(p));
    return a;
}
__device__ __forceinline__ void cp_async16(uint32_t dst, const void* src) {
    asm volatile("cp.async.cg.shared.global [%0], [%1], 16;"
                 :: "r"(dst), "l"(src));
}
__device__ __forceinline__ void cp_async_mbar_arrive(uint32_t mbar) {
    asm volatile("cp.async.mbarrier.arrive.noinc.shared::cta.b64 [%0];"
                 :: "r"(mbar) : "memory");
}
#define MBARRIER_INIT(mbar, cnt) \
    asm volatile("mbarrier.init.shared.b64 [%0], %1;" \
                 :: "r"((uint32_t)(mbar)), "r"((uint32_t)(cnt)) : "memory")
#define MBARRIER_ARRIVE(mbar) \
    asm volatile("mbarrier.arrive.shared.b64 _, [%0];" \
                 :: "r"((uint32_t)(mbar)) : "memory")
#define MBARRIER_WAIT_PARITY(mbar, parity) do {                              \
    uint32_t _m = (uint32_t)(mbar); uint32_t _p = (uint32_t)(parity);        \
    uint32_t _done;                                                          \
    asm volatile(                                                            \
        "{\n\t.reg .pred p;\n\t"                                             \
        "mbarrier.try_wait.parity.acquire.cta.shared::cta.b64 p, [%1], %2;\n\t" \
        "selp.b32 %0, 1, 0, p;\n\t}"                                         \
        : "=r"(_done) : "r"(_m), "r"(_p) : "memory");                        \
    if (!_done) {                                                            \
        asm volatile(                                                        \
            "{\n\t.reg .pred P1;\n\t"                                        \
            "WAIT_LOOP_%=:\n\t"                                              \
            "mbarrier.try_wait.parity.acquire.cta.shared::cta.b64 P1, [%0], %1, 0x989680;\n\t" \
            "@P1 bra.uni WAIT_DONE_%=;\n\t"                                  \
            "bra.uni WAIT_LOOP_%=;\n\t"                                      \
            "WAIT_DONE_%=:\n\t}"                                             \
            :: "r"(_m), "r"(_p) : "memory");                                 \
    }                                                                        \
} while (0)

// ---------------- prep ----------------
__global__ __launch_bounds__(256) void fused_prep(
    const float* __restrict__ x, __half* __restrict__ xf,
    __half* __restrict__ xT, float* __restrict__ rowsum)
{
    __shared__ float t[32][33];
    const size_t base = (size_t)blockIdx.z * SEQ * HID;
    const int c0 = blockIdx.x * 32;   // hid
    const int r0 = blockIdx.y * 32;   // seq
    const int tx = threadIdx.x, ty = threadIdx.y;

#pragma unroll
    for (int j = 0; j < 4; j++) {
        int r = r0 + ty + j * 8;
        size_t o = base + (size_t)r * HID + c0 + tx;
        float v = x[o];
        t[ty + j * 8][tx] = v;
        xf[o] = __float2half_rn(v);
    }
    if (blockIdx.x == 0 && blockIdx.z == 0)
        rowsum[blockIdx.y * 256 + ty * 32 + tx] = 0.f;
    __syncthreads();
#pragma unroll
    for (int j = 0; j < 4; j++) {
        float v = t[tx][ty + j * 8];
        size_t o = base + (size_t)(c0 + ty + j * 8) * SEQ + r0 + tx;
        xT[o] = __float2half_rn(v);
    }
}

__global__ __launch_bounds__(256) void transpose_w(
    const float* __restrict__ Wq, const float* __restrict__ Wk,
    __half* __restrict__ WT)
{
    __shared__ float t[32][33];
    const float* src = blockIdx.z ? Wk : Wq;
    __half* dst = WT + (size_t)blockIdx.z * HID * HID;
    int c0 = blockIdx.x * 32, r0 = blockIdx.y * 32;
    int tx = threadIdx.x, ty = threadIdx.y;
#pragma unroll
    for (int j = 0; j < 4; j++)
        t[ty + j * 8][tx] = src[(size_t)(r0 + ty + j * 8) * HID + c0 + tx];
    __syncthreads();
#pragma unroll
    for (int j = 0; j < 4; j++)
        dst[(size_t)(c0 + ty + j * 8) * HID + r0 + tx] =
            __float2half_rn(t[tx][ty + j * 8]);
}

// ===========================================================================
// fp16 HMMA GEMM, mbarrier 3-stage pipeline.
// CTA 128x128 with 128 threads (4 warps, 2x2 grid), warp tile 64x64,
// K-chunk 64, smem row stride 144B.
// full[s]: count 128 (cp.async noinc); empty[s]: count 4 (1/warp).
// ===========================================================================
#define ROW_BYTES   144
#define PLANE_BYTES (128 * ROW_BYTES)     // 18432
#define STAGE_BYTES (2 * PLANE_BYTES)     // 36864
#define NSTAGES     3
#define MBAR_AREA   128
#define GSMEM_TOTAL (MBAR_AREA + NSTAGES * STAGE_BYTES)   // 110720

__global__ __launch_bounds__(128, 2) void gemm_f16(
    const __half* __restrict__ Ap, long long sAb,
    const __half* __restrict__ Bp, long long sBb,
    const float* __restrict__ bias, const float* __restrict__ bias2,
    float scale,
    float* __restrict__ Cf, __half* __restrict__ Ch,
    float* __restrict__ rowsum,
    long long sCb, int N, int K)
{
    extern __shared__ __align__(16) char smem[];

    const int tid = threadIdx.x;
    const int wid = tid >> 5;
    const int lid = tid & 31;
    const int warp_m = wid & 1;       // 0..1 -> 64-row slice
    const int warp_n = wid >> 1;      // 0..1 -> 64-col slice
    const int row0 = blockIdx.y * 128;
    const int col0 = blockIdx.x * 128;
    const int z = blockIdx.z;

    const __half* srcA = Ap + (size_t)z * sAb + (size_t)row0 * K;
    const __half* srcB = Bp + (size_t)z * sBb + (size_t)col0 * K;

    const uint32_t smb = smem_to_u32(smem);
    const uint32_t tiles = smb + MBAR_AREA;

    if (tid == 0) {
#pragma unroll
        for (int s = 0; s < NSTAGES; s++) {
            MBARRIER_INIT(smb + s * 16, 128);
            MBARRIER_INIT(smb + s * 16 + 8, 4);
        }
    }
    __syncthreads();

    const int ld_r = tid >> 3;        // 0..15 (x8 passes of 16 rows)
    const int ld_ch = tid & 7;        // 16B chunk in 128B payload

    const int rA = warp_m * 64 + (lid & 15);
    const uint32_t aoff = (uint32_t)(rA * ROW_BYTES + ((lid >> 4) & 1) * 16);
    const int rB = warp_n * 64 + (lid & 7) + ((lid >> 4) & 1) * 8;
    const uint32_t boff = (uint32_t)(rB * ROW_BYTES + ((lid >> 3) & 1) * 16);

    float d[4][8][4];
#pragma unroll
    for (int i = 0; i < 4; i++)
#pragma unroll
        for (int j = 0; j < 8; j++)
#pragma unroll
            for (int c = 0; c < 4; c++) d[i][j][c] = 0.f;

    const int nchunks = K >> 6;

    auto issue = [&](int ci, int st) {
        const int k0 = ci << 6;
        const uint32_t sb = tiles + st * STAGE_BYTES;
#pragma unroll
        for (int t = 0; t < 8; t++) {
            int r = ld_r + t * 16;
            cp_async16(sb + r * ROW_BYTES + ld_ch * 16,
                       srcA + (size_t)r * K + k0 + ld_ch * 8);
        }
#pragma unroll
        for (int t = 0; t < 8; t++) {
            int r = ld_r + t * 16;
            cp_async16(sb + PLANE_BYTES + r * ROW_BYTES + ld_ch * 16,
                       srcB + (size_t)r * K + k0 + ld_ch * 8);
        }
        cp_async_mbar_arrive(smb + st * 16);   // full[st], noinc
    };

    int p_st = 0, p_ph = 1;
    int c_st = 0, c_ph = 0;

    // prologue: fill stages 0,1 with chunks 0,1
#pragma unroll
    for (int s = 0; s < 2; s++) {
        MBARRIER_WAIT_PARITY(smb + p_st * 16 + 8, p_ph);   // passes immediately
        issue(s, p_st);
        if (++p_st == NSTAGES) { p_st = 0; p_ph ^= 1; }
    }

    for (int ci = 0; ci < nchunks; ci++) {
        const int nx = ci + 2;
        if (nx < nchunks) {
            MBARRIER_WAIT_PARITY(smb + p_st * 16 + 8, p_ph);
            issue(nx, p_st);
            if (++p_st == NSTAGES) { p_st = 0; p_ph ^= 1; }
        }

        MBARRIER_WAIT_PARITY(smb + c_st * 16, c_ph);

        const uint32_t sb = tiles + c_st * STAGE_BYTES;
        const uint32_t pA = sb;
        const uint32_t pB = sb + PLANE_BYTES;

#pragma unroll
        for (int ks = 0; ks < 4; ks++) {
            const uint32_t kb = ks * 32;
            uint32_t bh[16];
#pragma unroll
            for (int nj = 0; nj < 4; nj++)
                ldsm_x4(bh + nj * 4, pB + boff + kb + nj * 16 * ROW_BYTES);
#pragma unroll
            for (int mi = 0; mi < 4; mi++) {
                uint32_t ah[4];
                ldsm_x4(ah, pA + aoff + kb + mi * 16 * ROW_BYTES);
#pragma unroll
                for (int ni = 0; ni < 8; ni++)
                    mma_f16(d[mi][ni], ah, bh + ni * 2);
            }
        }

        __syncwarp();
        if (lid == 0) MBARRIER_ARRIVE(smb + c_st * 16 + 8);   // empty[c_st]
        if (++c_st == NSTAGES) { c_st = 0; c_ph ^= 1; }
    }

    // ---- epilogue ----
    const int tr = lid >> 2;
    const int tc = (lid & 3) * 2;

    if (Cf) {
        // out GEMM: normalize by rowsum
#pragma unroll
        for (int mi = 0; mi < 4; mi++) {
            int r0g = row0 + warp_m * 64 + mi * 16 + tr;
            float inv0 = 1.0f / rowsum[z * SEQ + r0g];
            float inv1 = 1.0f / rowsum[z * SEQ + r0g + 8];
#pragma unroll
            for (int ni = 0; ni < 8; ni++) {
                int cg = col0 + warp_n * 64 + ni * 8 + tc;
                float* dst0 = Cf + (size_t)z * sCb + (size_t)r0g * N + cg;
                float* dst1 = dst0 + (size_t)8 * N;
                *(float2*)dst0 = make_float2(d[mi][ni][0] * inv0, d[mi][ni][1] * inv0);
                *(float2*)dst1 = make_float2(d[mi][ni][2] * inv1, d[mi][ni][3] * inv1);
            }
        }
    } else if (rowsum) {
        // scores: e = exp(d*scale) -> fp16, accumulate row sums
        float rs[4][2];
#pragma unroll
        for (int mi = 0; mi < 4; mi++) { rs[mi][0] = 0.f; rs[mi][1] = 0.f; }
#pragma unroll
        for (int mi = 0; mi < 4; mi++) {
            int r0g = row0 + warp_m * 64 + mi * 16 + tr;
#pragma unroll
            for (int ni = 0; ni < 8; ni++) {
                int cg = col0 + warp_n * 64 + ni * 8 + tc;
                float e0 = __expf(d[mi][ni][0] * scale);
                float e1 = __expf(d[mi][ni][1] * scale);
                float e2 = __expf(d[mi][ni][2] * scale);
                float e3 = __expf(d[mi][ni][3] * scale);
                rs[mi][0] += e0 + e1;
                rs[mi][1] += e2 + e3;
                __half2 p0; p0.x = __float2half_rn(e0); p0.y = __float2half_rn(e1);
                __half2 p1; p1.x = __float2half_rn(e2); p1.y = __float2half_rn(e3);
                size_t o0 = (size_t)z * sCb + (size_t)r0g * N + cg;
                *(__half2*)(Ch + o0) = p0;
                *(__half2*)(Ch + o0 + (size_t)8 * N) = p1;
            }
        }
#pragma unroll
        for (int mi = 0; mi < 4; mi++) {
#pragma unroll
            for (int h = 0; h < 2; h++) {
                float v = rs[mi][h];
                v += __shfl_xor_sync(0xffffffff, v, 1);
                v += __shfl_xor_sync(0xffffffff, v, 2);
                if ((lid & 3) == 0) {
                    int r = row0 + warp_m * 64 + mi * 16 + tr + h * 8;
                    atomicAdd(rowsum + z * SEQ + r, v);
                }
            }
        }
    } else {
        // projection: d + bias[z] -> fp16
        const float* bz = (bias2 && z == 1) ? bias2 : bias;
#pragma unroll
        for (int mi = 0; mi < 4; mi++) {
            int r0g = row0 + warp_m * 64 + mi * 16 + tr;
#pragma unroll
            for (int ni = 0; ni < 8; ni++) {
                int cg = col0 + warp_n * 64 + ni * 8 + tc;
                float b0 = bz[cg], b1 = bz[cg + 1];
#pragma unroll
                for (int half = 0; half < 2; half++) {
                    __half2 p;
                    p.x = __float2half_rn(d[mi][ni][half * 2 + 0] + b0);
                    p.y = __float2half_rn(d[mi][ni][half * 2 + 1] + b1);
                    size_t o = (size_t)z * sCb + (size_t)(r0g + half * 8) * N + cg;
                    *(__half2*)(Ch + o) = p;
                }
            }
        }
    }
}

// ---------------------------------------------------------------------------
extern "C" void kernel_launch(void* const* d_in, const int* in_sizes, int n_in,
                              void* d_out, int out_size)
{
    const float* x  = (const float*)d_in[0];  // [8,2048,512]
    const float* Wq = (const float*)d_in[1];  // [512,512]
    const float* bq = (const float*)d_in[2];  // [512]
    const float* Wk = (const float*)d_in[3];  // [512,512]
    const float* bk = (const float*)d_in[4];  // [512]
    float* out = (float*)d_out;               // [8,2048,512]

    cudaFuncSetAttribute(gemm_f16,
                         cudaFuncAttributeMaxDynamicSharedMemorySize, GSMEM_TOTAL);

    __half *xf, *xT, *WT, *QKf, *Ef;
    float* rowsum;
    cudaGetSymbolAddress((void**)&xf,  g_xf);
    cudaGetSymbolAddress((void**)&xT,  g_xT);
    cudaGetSymbolAddress((void**)&WT,  g_WT);
    cudaGetSymbolAddress((void**)&QKf, g_QKf);
    cudaGetSymbolAddress((void**)&Ef,  g_Ef);
    cudaGetSymbolAddress((void**)&rowsum, g_rowsum);

    const float scaleQ = 1.0f / sqrtf((float)HID);

    // --- prep ---
    {
        dim3 g(HID / 32, SEQ / 32, BATCH);
        dim3 b(32, 8);
        fused_prep<<<g, b>>>(x, xf, xT, rowsum);
    }
    {
        dim3 g(HID / 32, HID / 32, 2);
        dim3 b(32, 8);
        transpose_w<<<g, b>>>(Wq, Wk, WT);
    }

    // --- merged Q/K projections: z=0->Q, z=1->K ---
    {
        dim3 grid(HID / 128, MROWS / 128, 2);
        gemm_f16<<<grid, 128, GSMEM_TOTAL>>>(
            xf, 0, WT, (long long)HID * HID,
            bq, bk, 1.0f,
            nullptr, QKf, nullptr, (long long)MROWS * HID, HID, HID);
    }
    // --- scores+exp: E = exp((Q@K^T)/sqrt(D)) -> fp16 + rowsum ---
    {
        dim3 grid(SEQ / 128, SEQ / 128, BATCH);
        gemm_f16<<<grid, 128, GSMEM_TOTAL>>>(
            QKf, (long long)SEQ * HID,
            QKf + (size_t)MROWS * HID, (long long)SEQ * HID,
            nullptr, nullptr, scaleQ,
            nullptr, Ef, rowsum, (long long)SEQ * SEQ, SEQ, HID);
    }
    // --- out = (E @ xT^T) / rowsum  (per batch 2048x512, K=2048) ---
    {
        dim3 grid(HID / 128, SEQ / 128, BATCH);
        gemm_f16<<<grid, 128, GSMEM_TOTAL>>>(
            Ef, (long long)SEQ * SEQ,
            xT, (long long)HID * SEQ,
            nullptr, nullptr, 1.0f,
            out, nullptr, rowsum, (long long)SEQ * HID, HID, SEQ);
    }
}

// round 15
// speedup vs baseline: 3.2962x; 1.0087x over previous
#include <cuda_runtime.h>
#include <cuda_fp16.h>
#include <cstdint>
#include <math.h>

// ===========================================================================
// SelfAttention, fp16 HMMA pipeline (base sm_103 ISA), R14: projection
// elimination via bilinear identity:
//   QK^T = x G x^T + u 1^T + 1 v^T,  G = Wq Wk^T,
//   u = x(Wq bk) + bq.bk,  v = x(Wk bq)
// Launches:
//   fused_prep: x -> xf, xT, rowsum=0
//   cast_w:     Wq,Wk -> fp16
//   wvec:       w1=Wq bk, w2=Wk bq, c0=bq.bk      (fp32)
//   GT-GEMM:    GT = Wk @ Wq^T                    (fp16, tensor core)
//   uv:         u = xf.w1 + c0, v = xf.w2         (fp32)
//   y-GEMM:     y = xf @ GT^T                     (fp16)
//   scores:     E = exp((y.x^T + u + v)*scale)    (fp16 + rowsum)
//   out:        out = (E @ xT^T) / rowsum         (fp32)
// ===========================================================================

#define BATCH 8
#define SEQ   2048
#define HID   512
#define MROWS (BATCH * SEQ)   // 16384

// ---------------- scratch (__device__ globals) ----------------
__device__ __half g_xf [MROWS * HID];
__device__ __half g_xT [MROWS * HID];          // per-batch [512,2048]
__device__ __half g_Wqf[HID * HID];
__device__ __half g_Wkf[HID * HID];
__device__ __half g_GT [HID * HID];            // GT[c,d] = G[d,c]
__device__ __half g_y  [MROWS * HID];          // y = x @ G
__device__ __half g_Ef [(size_t)BATCH * SEQ * SEQ]; // 67 MB exp(S)
__device__ float  g_rowsum[MROWS];
__device__ float  g_wvec[2 * HID + 32];        // w1 | w2 | c0 at [1024]
__device__ float  g_u[MROWS];
__device__ float  g_v[MROWS];

// ---------------- asm helpers (base ISA) ----------------
__device__ __forceinline__ void ldsm_x4(uint32_t* r, uint32_t addr) {
    asm volatile("ldmatrix.sync.aligned.m8n8.x4.shared.b16 {%0,%1,%2,%3}, [%4];"
                 : "=r"(r[0]), "=r"(r[1]), "=r"(r[2]), "=r"(r[3]) : "r"(addr));
}
__device__ __forceinline__ void mma_f16(float* d, const uint32_t* a, const uint32_t* b) {
    asm volatile(
        "mma.sync.aligned.m16n8k16.row.col.f32.f16.f16.f32 "
        "{%0,%1,%2,%3}, {%4,%5,%6,%7}, {%8,%9}, {%0,%1,%2,%3};"
        : "+f"(d[0]), "+f"(d[1]), "+f"(d[2]), "+f"(d[3])
        : "r"(a[0]), "r"(a[1]), "r"(a[2]), "r"(a[3]), "r"(b[0]), "r"(b[1]));
}
__device__ __forceinline__ uint32_t smem_to_u32(const void* p) {
    uint32_t a;
    asm("{ .reg .u64 t; cvta.to.shared.u64 t, %1; cvt.u32.u64 %0, t; }"
        : "=r"(a) : "l"(p));
    return a;
}
__device__ __forceinline__ void cp_async16(uint32_t dst, const void* src) {
    asm volatile("cp.async.cg.shared.global [%0], [%1], 16;"
                 :: "r"(dst), "l"(src));
}
__device__ __forceinline__ void cp_async_mbar_arrive(uint32_t mbar) {
    asm volatile("cp.async.mbarrier.arrive.noinc.shared::cta.b64 [%0];"
                 :: "r"(mbar) : "memory");
}
#define MBARRIER_INIT(mbar, cnt) \
    asm volatile("mbarrier.init.shared.b64 [%0], %1;" \
                 :: "r"((uint32_t)(mbar)), "r"((uint32_t)(cnt)) : "memory")
#define MBARRIER_ARRIVE(mbar) \
    asm volatile("mbarrier.arrive.shared.b64 _, [%0];" \
                 :: "r"((uint32_t)(mbar)) : "memory")
#define MBARRIER_WAIT_PARITY(mbar, parity) do {                              \
    uint32_t _m = (uint32_t)(mbar); uint32_t _p = (uint32_t)(parity);        \
    uint32_t _done;                                                          \
    asm volatile(                                                            \
        "{\n\t.reg .pred p;\n\t"                                             \
        "mbarrier.try_wait.parity.acquire.cta.shared::cta.b64 p, [%1], %2;\n\t" \
        "selp.b32 %0, 1, 0, p;\n\t}"                                         \
        : "=r"(_done) : "r"(_m), "r"(_p) : "memory");                        \
    if (!_done) {                                                            \
        asm volatile(                                                        \
            "{\n\t.reg .pred P1;\n\t"                                        \
            "WAIT_LOOP_%=:\n\t"                                              \
            "mbarrier.try_wait.parity.acquire.cta.shared::cta.b64 P1, [%0], %1, 0x989680;\n\t" \
            "@P1 bra.uni WAIT_DONE_%=;\n\t"                                  \
            "bra.uni WAIT_LOOP_%=;\n\t"                                      \
            "WAIT_DONE_%=:\n\t}"                                             \
            :: "r"(_m), "r"(_p) : "memory");                                 \
    }                                                                        \
} while (0)

// ---------------- prep ----------------
__global__ __launch_bounds__(256) void fused_prep(
    const float* __restrict__ x, __half* __restrict__ xf,
    __half* __restrict__ xT, float* __restrict__ rowsum)
{
    __shared__ float t[32][33];
    const size_t base = (size_t)blockIdx.z * SEQ * HID;
    const int c0 = blockIdx.x * 32;   // hid
    const int r0 = blockIdx.y * 32;   // seq
    const int tx = threadIdx.x, ty = threadIdx.y;

#pragma unroll
    for (int j = 0; j < 4; j++) {
        int r = r0 + ty + j * 8;
        size_t o = base + (size_t)r * HID + c0 + tx;
        float v = x[o];
        t[ty + j * 8][tx] = v;
        xf[o] = __float2half_rn(v);
    }
    if (blockIdx.x == 0 && blockIdx.z == 0)
        rowsum[blockIdx.y * 256 + ty * 32 + tx] = 0.f;
    __syncthreads();
#pragma unroll
    for (int j = 0; j < 4; j++) {
        float v = t[tx][ty + j * 8];
        size_t o = base + (size_t)(c0 + ty + j * 8) * SEQ + r0 + tx;
        xT[o] = __float2half_rn(v);
    }
}

__global__ __launch_bounds__(256) void cast_w(
    const float* __restrict__ Wq, const float* __restrict__ Wk,
    __half* __restrict__ Wqf, __half* __restrict__ Wkf)
{
    int i = blockIdx.x * 256 + threadIdx.x;
    if (i < HID * HID) {
        Wqf[i] = __float2half_rn(Wq[i]);
        Wkf[i] = __float2half_rn(Wk[i]);
    }
}

// w1[d]=Wq[d,:].bk, w2[d]=Wk[d,:].bq, c0=bq.bk  (fp32, warp per row)
__global__ __launch_bounds__(256) void wvec(
    const float* __restrict__ Wq, const float* __restrict__ Wk,
    const float* __restrict__ bq, const float* __restrict__ bk,
    float* __restrict__ wv)
{
    int gw = blockIdx.x * 8 + (threadIdx.x >> 5);
    int lane = threadIdx.x & 31;
    float s = 0.f;
    if (gw < HID) {
#pragma unroll
        for (int j = 0; j < 16; j++) {
            int idx = j * 32 + lane;
            s += Wq[(size_t)gw * HID + idx] * bk[idx];
        }
    } else if (gw < 2 * HID) {
        int d = gw - HID;
#pragma unroll
        for (int j = 0; j < 16; j++) {
            int idx = j * 32 + lane;
            s += Wk[(size_t)d * HID + idx] * bq[idx];
        }
    } else if (gw == 2 * HID) {
#pragma unroll
        for (int j = 0; j < 16; j++) {
            int idx = j * 32 + lane;
            s += bq[idx] * bk[idx];
        }
    } else {
        return;
    }
#pragma unroll
    for (int o = 16; o > 0; o >>= 1) s += __shfl_xor_sync(0xffffffff, s, o);
    if (lane == 0) wv[gw] = s;
}

// u[i] = xf[i,:].w1 + c0 ; v[i] = xf[i,:].w2   (warp per row)
__global__ __launch_bounds__(256) void uv_kernel(
    const __half* __restrict__ xf, const float* __restrict__ wv,
    float* __restrict__ u, float* __restrict__ v)
{
    __shared__ float w1s[HID], w2s[HID];
    for (int i = threadIdx.x; i < HID; i += 256) {
        w1s[i] = wv[i];
        w2s[i] = wv[HID + i];
    }
    __syncthreads();
    int row = blockIdx.x * 8 + (threadIdx.x >> 5);
    int lane = threadIdx.x & 31;
    float a = 0.f, b = 0.f;
#pragma unroll
    for (int j = 0; j < 16; j++) {
        int idx = j * 32 + lane;
        float xv = __half2float(xf[(size_t)row * HID + idx]);
        a += xv * w1s[idx];
        b += xv * w2s[idx];
    }
#pragma unroll
    for (int o = 16; o > 0; o >>= 1) {
        a += __shfl_xor_sync(0xffffffff, a, o);
        b += __shfl_xor_sync(0xffffffff, b, o);
    }
    if (lane == 0) {
        u[row] = a + wv[2 * HID];
        v[row] = b;
    }
}

// ===========================================================================
// fp16 HMMA GEMM, mbarrier 3-stage pipeline (R13 core, unchanged mainloop).
// CTA 128x128, 128 threads (4 warps, 2x2), warp tile 64x64, K-chunk 64.
// Epilogues: Cf       : d / rowsum[row] -> fp32            (out)
//            rowsum   : exp((d+u[i]+v[j])*scale) + rowsum  (scores)
//            else     : d -> fp16                          (GT / y)
// ===========================================================================
#define ROW_BYTES   144
#define PLANE_BYTES (128 * ROW_BYTES)     // 18432
#define STAGE_BYTES (2 * PLANE_BYTES)     // 36864
#define NSTAGES     3
#define MBAR_AREA   128
#define GSMEM_TOTAL (MBAR_AREA + NSTAGES * STAGE_BYTES)   // 110720

__global__ __launch_bounds__(128, 2) void gemm_f16(
    const __half* __restrict__ Ap, long long sAb,
    const __half* __restrict__ Bp, long long sBb,
    const float* __restrict__ u, const float* __restrict__ v,
    float scale,
    float* __restrict__ Cf, __half* __restrict__ Ch,
    float* __restrict__ rowsum,
    long long sCb, int N, int K)
{
    extern __shared__ __align__(16) char smem[];

    const int tid = threadIdx.x;
    const int wid = tid >> 5;
    const int lid = tid & 31;
    const int warp_m = wid & 1;
    const int warp_n = wid >> 1;
    const int row0 = blockIdx.y * 128;
    const int col0 = blockIdx.x * 128;
    const int z = blockIdx.z;

    const __half* srcA = Ap + (size_t)z * sAb + (size_t)row0 * K;
    const __half* srcB = Bp + (size_t)z * sBb + (size_t)col0 * K;

    const uint32_t smb = smem_to_u32(smem);
    const uint32_t tiles = smb + MBAR_AREA;

    if (tid == 0) {
#pragma unroll
        for (int s = 0; s < NSTAGES; s++) {
            MBARRIER_INIT(smb + s * 16, 128);
            MBARRIER_INIT(smb + s * 16 + 8, 4);
        }
    }
    __syncthreads();

    const int ld_r = tid >> 3;
    const int ld_ch = tid & 7;

    const int rA = warp_m * 64 + (lid & 15);
    const uint32_t aoff = (uint32_t)(rA * ROW_BYTES + ((lid >> 4) & 1) * 16);
    const int rB = warp_n * 64 + (lid & 7) + ((lid >> 4) & 1) * 8;
    const uint32_t boff = (uint32_t)(rB * ROW_BYTES + ((lid >> 3) & 1) * 16);

    float d[4][8][4];
#pragma unroll
    for (int i = 0; i < 4; i++)
#pragma unroll
        for (int j = 0; j < 8; j++)
#pragma unroll
            for (int c = 0; c < 4; c++) d[i][j][c] = 0.f;

    const int nchunks = K >> 6;

    auto issue = [&](int ci, int st) {
        const int k0 = ci << 6;
        const uint32_t sb = tiles + st * STAGE_BYTES;
#pragma unroll
        for (int t = 0; t < 8; t++) {
            int r = ld_r + t * 16;
            cp_async16(sb + r * ROW_BYTES + ld_ch * 16,
                       srcA + (size_t)r * K + k0 + ld_ch * 8);
        }
#pragma unroll
        for (int t = 0; t < 8; t++) {
            int r = ld_r + t * 16;
            cp_async16(sb + PLANE_BYTES + r * ROW_BYTES + ld_ch * 16,
                       srcB + (size_t)r * K + k0 + ld_ch * 8);
        }
        cp_async_mbar_arrive(smb + st * 16);
    };

    int p_st = 0, p_ph = 1;
    int c_st = 0, c_ph = 0;

#pragma unroll
    for (int s = 0; s < 2; s++) {
        MBARRIER_WAIT_PARITY(smb + p_st * 16 + 8, p_ph);
        issue(s, p_st);
        if (++p_st == NSTAGES) { p_st = 0; p_ph ^= 1; }
    }

    for (int ci = 0; ci < nchunks; ci++) {
        const int nx = ci + 2;
        if (nx < nchunks) {
            MBARRIER_WAIT_PARITY(smb + p_st * 16 + 8, p_ph);
            issue(nx, p_st);
            if (++p_st == NSTAGES) { p_st = 0; p_ph ^= 1; }
        }

        MBARRIER_WAIT_PARITY(smb + c_st * 16, c_ph);

        const uint32_t sb = tiles + c_st * STAGE_BYTES;
        const uint32_t pA = sb;
        const uint32_t pB = sb + PLANE_BYTES;

#pragma unroll
        for (int ks = 0; ks < 4; ks++) {
            const uint32_t kb = ks * 32;
            uint32_t bh[16];
#pragma unroll
            for (int nj = 0; nj < 4; nj++)
                ldsm_x4(bh + nj * 4, pB + boff + kb + nj * 16 * ROW_BYTES);
#pragma unroll
            for (int mi = 0; mi < 4; mi++) {
                uint32_t ah[4];
                ldsm_x4(ah, pA + aoff + kb + mi * 16 * ROW_BYTES);
#pragma unroll
                for (int ni = 0; ni < 8; ni++)
                    mma_f16(d[mi][ni], ah, bh + ni * 2);
            }
        }

        __syncwarp();
        if (lid == 0) MBARRIER_ARRIVE(smb + c_st * 16 + 8);
        if (++c_st == NSTAGES) { c_st = 0; c_ph ^= 1; }
    }

    // ---- epilogue ----
    const int tr = lid >> 2;
    const int tc = (lid & 3) * 2;

    if (Cf) {
        // out GEMM: normalize by rowsum
#pragma unroll
        for (int mi = 0; mi < 4; mi++) {
            int r0g = row0 + warp_m * 64 + mi * 16 + tr;
            float inv0 = 1.0f / rowsum[z * SEQ + r0g];
            float inv1 = 1.0f / rowsum[z * SEQ + r0g + 8];
#pragma unroll
            for (int ni = 0; ni < 8; ni++) {
                int cg = col0 + warp_n * 64 + ni * 8 + tc;
                float* dst0 = Cf + (size_t)z * sCb + (size_t)r0g * N + cg;
                float* dst1 = dst0 + (size_t)8 * N;
                *(float2*)dst0 = make_float2(d[mi][ni][0] * inv0, d[mi][ni][1] * inv0);
                *(float2*)dst1 = make_float2(d[mi][ni][2] * inv1, d[mi][ni][3] * inv1);
            }
        }
    } else if (rowsum) {
        // scores: e = exp((d + u[i] + v[j])*scale) -> fp16 + rowsum
        float rs[4][2];
#pragma unroll
        for (int mi = 0; mi < 4; mi++) { rs[mi][0] = 0.f; rs[mi][1] = 0.f; }
#pragma unroll
        for (int mi = 0; mi < 4; mi++) {
            int r0g = row0 + warp_m * 64 + mi * 16 + tr;
            float uu0 = u[z * SEQ + r0g];
            float uu1 = u[z * SEQ + r0g + 8];
#pragma unroll
            for (int ni = 0; ni < 8; ni++) {
                int cg = col0 + warp_n * 64 + ni * 8 + tc;
                float vv0 = v[z * SEQ + cg];
                float vv1 = v[z * SEQ + cg + 1];
                float e0 = __expf((d[mi][ni][0] + uu0 + vv0) * scale);
                float e1 = __expf((d[mi][ni][1] + uu0 + vv1) * scale);
                float e2 = __expf((d[mi][ni][2] + uu1 + vv0) * scale);
                float e3 = __expf((d[mi][ni][3] + uu1 + vv1) * scale);
                rs[mi][0] += e0 + e1;
                rs[mi][1] += e2 + e3;
                __half2 p0; p0.x = __float2half_rn(e0); p0.y = __float2half_rn(e1);
                __half2 p1; p1.x = __float2half_rn(e2); p1.y = __float2half_rn(e3);
                size_t o0 = (size_t)z * sCb + (size_t)r0g * N + cg;
                *(__half2*)(Ch + o0) = p0;
                *(__half2*)(Ch + o0 + (size_t)8 * N) = p1;
            }
        }
#pragma unroll
        for (int mi = 0; mi < 4; mi++) {
#pragma unroll
            for (int h = 0; h < 2; h++) {
                float s = rs[mi][h];
                s += __shfl_xor_sync(0xffffffff, s, 1);
                s += __shfl_xor_sync(0xffffffff, s, 2);
                if ((lid & 3) == 0) {
                    int r = row0 + warp_m * 64 + mi * 16 + tr + h * 8;
                    atomicAdd(rowsum + z * SEQ + r, s);
                }
            }
        }
    } else {
        // plain fp16 store (GT-GEMM, y-GEMM)
#pragma unroll
        for (int mi = 0; mi < 4; mi++) {
            int r0g = row0 + warp_m * 64 + mi * 16 + tr;
#pragma unroll
            for (int ni = 0; ni < 8; ni++) {
                int cg = col0 + warp_n * 64 + ni * 8 + tc;
#pragma unroll
                for (int half = 0; half < 2; half++) {
                    __half2 p;
                    p.x = __float2half_rn(d[mi][ni][half * 2 + 0]);
                    p.y = __float2half_rn(d[mi][ni][half * 2 + 1]);
                    size_t o = (size_t)z * sCb + (size_t)(r0g + half * 8) * N + cg;
                    *(__half2*)(Ch + o) = p;
                }
            }
        }
    }
}

// ---------------------------------------------------------------------------
extern "C" void kernel_launch(void* const* d_in, const int* in_sizes, int n_in,
                              void* d_out, int out_size)
{
    const float* x  = (const float*)d_in[0];  // [8,2048,512]
    const float* Wq = (const float*)d_in[1];  // [512,512]
    const float* bq = (const float*)d_in[2];  // [512]
    const float* Wk = (const float*)d_in[3];  // [512,512]
    const float* bk = (const float*)d_in[4];  // [512]
    float* out = (float*)d_out;               // [8,2048,512]

    cudaFuncSetAttribute(gemm_f16,
                         cudaFuncAttributeMaxDynamicSharedMemorySize, GSMEM_TOTAL);

    __half *xf, *xT, *Wqf, *Wkf, *GT, *yf, *Ef;
    float *rowsum, *wv, *u, *v;
    cudaGetSymbolAddress((void**)&xf,  g_xf);
    cudaGetSymbolAddress((void**)&xT,  g_xT);
    cudaGetSymbolAddress((void**)&Wqf, g_Wqf);
    cudaGetSymbolAddress((void**)&Wkf, g_Wkf);
    cudaGetSymbolAddress((void**)&GT,  g_GT);
    cudaGetSymbolAddress((void**)&yf,  g_y);
    cudaGetSymbolAddress((void**)&Ef,  g_Ef);
    cudaGetSymbolAddress((void**)&rowsum, g_rowsum);
    cudaGetSymbolAddress((void**)&wv,  g_wvec);
    cudaGetSymbolAddress((void**)&u,   g_u);
    cudaGetSymbolAddress((void**)&v,   g_v);

    const float scaleQ = 1.0f / sqrtf((float)HID);

    // --- prep + weight prep ---
    {
        dim3 g(HID / 32, SEQ / 32, BATCH);
        dim3 b(32, 8);
        fused_prep<<<g, b>>>(x, xf, xT, rowsum);
    }
    cast_w<<<(HID * HID + 255) / 256, 256>>>(Wq, Wk, Wqf, Wkf);
    wvec<<<129, 256>>>(Wq, Wk, bq, bk, wv);

    // --- GT = Wk @ Wq^T (fp16, 512x512x512) ---
    {
        dim3 grid(HID / 128, HID / 128, 1);
        gemm_f16<<<grid, 128, GSMEM_TOTAL>>>(
            Wkf, 0, Wqf, 0, nullptr, nullptr, 1.0f,
            nullptr, GT, nullptr, 0, HID, HID);
    }
    // --- u, v vectors ---
    uv_kernel<<<MROWS / 8, 256>>>(xf, wv, u, v);

    // --- y = xf @ GT^T  (16384x512x512) ---
    {
        dim3 grid(HID / 128, MROWS / 128, 1);
        gemm_f16<<<grid, 128, GSMEM_TOTAL>>>(
            xf, 0, GT, 0, nullptr, nullptr, 1.0f,
            nullptr, yf, nullptr, 0, HID, HID);
    }
    // --- scores+exp: E = exp((y@x^T + u + v)/sqrt(D)) -> fp16 + rowsum ---
    {
        dim3 grid(SEQ / 128, SEQ / 128, BATCH);
        gemm_f16<<<grid, 128, GSMEM_TOTAL>>>(
            yf, (long long)SEQ * HID,
            xf, (long long)SEQ * HID,
            u, v, scaleQ,
            nullptr, Ef, rowsum, (long long)SEQ * SEQ, SEQ, HID);
    }
    // --- out = (E @ xT^T) / rowsum ---
    {
        dim3 grid(HID / 128, SEQ / 128, BATCH);
        gemm_f16<<<grid, 128, GSMEM_TOTAL>>>(
            Ef, (long long)SEQ * SEQ,
            xT, (long long)HID * SEQ,
            nullptr, nullptr, 1.0f,
            out, nullptr, rowsum, (long long)SEQ * HID, HID, SEQ);
    }
}

// round 16
// speedup vs baseline: 3.3753x; 1.0240x over previous
#include <cuda_runtime.h>
#include <cuda_fp16.h>
#include <cstdint>
#include <math.h>

// ===========================================================================
// SelfAttention, fp16 HMMA pipeline (base sm_103 ISA).
// R15: bilinear identity (R14) + overhead surgery:
//   - GT computed via split-K (64 CTAs) with fp32 atomic accumulation
//   - merged weight_prep (cast + Gacc zero + wvec)
//   - vectorized fused_prep (float4/uint2, 64x64 tiles)
// Pipeline:
//   weight_prep:  Wq,Wk->fp16; Gacc=0; w1=Wq bk, w2=Wk bq, c0=bq.bk
//   GT-splitK:    Gacc += Wk @ Wq^T (fp32 atomics)      [tensor core]
//   cast_G:       GT = fp16(Gacc)
//   fused_prep:   x -> xf, xT; rowsum=0
//   uv:           u = xf.w1 + c0, v = xf.w2
//   y-GEMM:       y = xf @ GT^T
//   scores:       E = exp((y.x^T + u + v)*scale) -> fp16 + rowsum
//   out:          out = (E @ xT^T) / rowsum -> fp32
// ===========================================================================

#define BATCH 8
#define SEQ   2048
#define HID   512
#define MROWS (BATCH * SEQ)   // 16384

// ---------------- scratch (__device__ globals) ----------------
__device__ __half g_xf [MROWS * HID];
__device__ __half g_xT [MROWS * HID];          // per-batch [512,2048]
__device__ __half g_Wqf[HID * HID];
__device__ __half g_Wkf[HID * HID];
__device__ float  g_Gacc[HID * HID];           // fp32 split-K accumulator
__device__ __half g_GT [HID * HID];            // GT[c,d] = G[d,c]
__device__ __half g_y  [MROWS * HID];          // y = x @ G
__device__ __half g_Ef [(size_t)BATCH * SEQ * SEQ]; // 67 MB exp(S)
__device__ float  g_rowsum[MROWS];
__device__ float  g_wvec[2 * HID + 32];        // w1 | w2 | c0 at [1024]
__device__ float  g_u[MROWS];
__device__ float  g_v[MROWS];

// ---------------- asm helpers (base ISA) ----------------
__device__ __forceinline__ void ldsm_x4(uint32_t* r, uint32_t addr) {
    asm volatile("ldmatrix.sync.aligned.m8n8.x4.shared.b16 {%0,%1,%2,%3}, [%4];"
                 : "=r"(r[0]), "=r"(r[1]), "=r"(r[2]), "=r"(r[3]) : "r"(addr));
}
__device__ __forceinline__ void mma_f16(float* d, const uint32_t* a, const uint32_t* b) {
    asm volatile(
        "mma.sync.aligned.m16n8k16.row.col.f32.f16.f16.f32 "
        "{%0,%1,%2,%3}, {%4,%5,%6,%7}, {%8,%9}, {%0,%1,%2,%3};"
        : "+f"(d[0]), "+f"(d[1]), "+f"(d[2]), "+f"(d[3])
        : "r"(a[0]), "r"(a[1]), "r"(a[2]), "r"(a[3]), "r"(b[0]), "r"(b[1]));
}
__device__ __forceinline__ uint32_t smem_to_u32(const void* p) {
    uint32_t a;
    asm("{ .reg .u64 t; cvta.to.shared.u64 t, %1; cvt.u32.u64 %0, t; }"
        : "=r"(a) : "l"(p));
    return a;
}
__device__ __forceinline__ void cp_async16(uint32_t dst, const void* src) {
    asm volatile("cp.async.cg.shared.global [%0], [%1], 16;"
                 :: "r"(dst), "l"(src));
}
__device__ __forceinline__ void cp_async_mbar_arrive(uint32_t mbar) {
    asm volatile("cp.async.mbarrier.arrive.noinc.shared::cta.b64 [%0];"
                 :: "r"(mbar) : "memory");
}
#define MBARRIER_INIT(mbar, cnt) \
    asm volatile("mbarrier.init.shared.b64 [%0], %1;" \
                 :: "r"((uint32_t)(mbar)), "r"((uint32_t)(cnt)) : "memory")
#define MBARRIER_ARRIVE(mbar) \
    asm volatile("mbarrier.arrive.shared.b64 _, [%0];" \
                 :: "r"((uint32_t)(mbar)) : "memory")
#define MBARRIER_WAIT_PARITY(mbar, parity) do {                              \
    uint32_t _m = (uint32_t)(mbar); uint32_t _p = (uint32_t)(parity);        \
    uint32_t _done;                                                          \
    asm volatile(                                                            \
        "{\n\t.reg .pred p;\n\t"                                             \
        "mbarrier.try_wait.parity.acquire.cta.shared::cta.b64 p, [%1], %2;\n\t" \
        "selp.b32 %0, 1, 0, p;\n\t}"                                         \
        : "=r"(_done) : "r"(_m), "r"(_p) : "memory");                        \
    if (!_done) {                                                            \
        asm volatile(                                                        \
            "{\n\t.reg .pred P1;\n\t"                                        \
            "WAIT_LOOP_%=:\n\t"                                              \
            "mbarrier.try_wait.parity.acquire.cta.shared::cta.b64 P1, [%0], %1, 0x989680;\n\t" \
            "@P1 bra.uni WAIT_DONE_%=;\n\t"                                  \
            "bra.uni WAIT_LOOP_%=;\n\t"                                      \
            "WAIT_DONE_%=:\n\t}"                                             \
            :: "r"(_m), "r"(_p) : "memory");                                 \
    }                                                                        \
} while (0)

// ---------------- prep: vectorized split + transpose ----------------
// 64x64 tiles. grid (HID/64, SEQ/64, BATCH), block 256.
__global__ __launch_bounds__(256) void fused_prep(
    const float* __restrict__ x, __half* __restrict__ xf,
    __half* __restrict__ xT, float* __restrict__ rowsum)
{
    __shared__ float t[64][65];
    const size_t base = (size_t)blockIdx.z * SEQ * HID;
    const int c0 = blockIdx.x * 64;   // hid
    const int r0 = blockIdx.y * 64;   // seq
    const int tid = threadIdx.x;

    // load + direct fp16 store: 64 rows x 16 float4
#pragma unroll
    for (int p = 0; p < 4; p++) {
        int idx = tid + p * 256;          // 0..1023
        int r = idx >> 4;                 // 0..63
        int c4 = idx & 15;                // float4 index
        float4 v = *(const float4*)(x + base + (size_t)(r0 + r) * HID + c0 + c4 * 4);
        t[r][c4 * 4 + 0] = v.x;
        t[r][c4 * 4 + 1] = v.y;
        t[r][c4 * 4 + 2] = v.z;
        t[r][c4 * 4 + 3] = v.w;
        __half2 h0, h1;
        h0.x = __float2half_rn(v.x); h0.y = __float2half_rn(v.y);
        h1.x = __float2half_rn(v.z); h1.y = __float2half_rn(v.w);
        uint2 pk;
        pk.x = *(uint32_t*)&h0;
        pk.y = *(uint32_t*)&h1;
        *(uint2*)(xf + base + (size_t)(r0 + r) * HID + c0 + c4 * 4) = pk;
    }
    if (blockIdx.x == 0 && blockIdx.z == 0) {
        rowsum[blockIdx.y * 512 + tid] = 0.f;
        rowsum[blockIdx.y * 512 + 256 + tid] = 0.f;
    }
    __syncthreads();
    // transposed store: xT row = hid (64), entries seq (64)
#pragma unroll
    for (int p = 0; p < 4; p++) {
        int idx = tid + p * 256;
        int c = idx >> 4;                 // hid within tile
        int r4 = idx & 15;                // seq quad
        float v0 = t[r4 * 4 + 0][c];
        float v1 = t[r4 * 4 + 1][c];
        float v2 = t[r4 * 4 + 2][c];
        float v3 = t[r4 * 4 + 3][c];
        __half2 h0, h1;
        h0.x = __float2half_rn(v0); h0.y = __float2half_rn(v1);
        h1.x = __float2half_rn(v2); h1.y = __float2half_rn(v3);
        uint2 pk;
        pk.x = *(uint32_t*)&h0;
        pk.y = *(uint32_t*)&h1;
        *(uint2*)(xT + base + (size_t)(c0 + c) * SEQ + r0 + r4 * 4) = pk;
    }
}

// ---------------- merged weight prep ----------------
// blocks 0..255:   cast Wq,Wk -> fp16 (1024 elems each) + zero Gacc slice
// blocks 256..384: wvec warps (w1, w2, c0)
__global__ __launch_bounds__(256) void weight_prep(
    const float* __restrict__ Wq, const float* __restrict__ Wk,
    const float* __restrict__ bq, const float* __restrict__ bk,
    __half* __restrict__ Wqf, __half* __restrict__ Wkf,
    float* __restrict__ Gacc, float* __restrict__ wv)
{
    const int b = blockIdx.x;
    if (b < 256) {
        int i0 = b * 1024 + threadIdx.x * 4;
#pragma unroll
        for (int k = 0; k < 4; k++) {
            int i = i0 + k;
            Wqf[i] = __float2half_rn(Wq[i]);
            Wkf[i] = __float2half_rn(Wk[i]);
            Gacc[i] = 0.f;
        }
        return;
    }
    int gw = (b - 256) * 8 + (threadIdx.x >> 5);
    int lane = threadIdx.x & 31;
    float s = 0.f;
    if (gw < HID) {
#pragma unroll
        for (int j = 0; j < 16; j++) {
            int idx = j * 32 + lane;
            s += Wq[(size_t)gw * HID + idx] * bk[idx];
        }
    } else if (gw < 2 * HID) {
        int d = gw - HID;
#pragma unroll
        for (int j = 0; j < 16; j++) {
            int idx = j * 32 + lane;
            s += Wk[(size_t)d * HID + idx] * bq[idx];
        }
    } else if (gw == 2 * HID) {
#pragma unroll
        for (int j = 0; j < 16; j++) {
            int idx = j * 32 + lane;
            s += bq[idx] * bk[idx];
        }
    } else {
        return;
    }
#pragma unroll
    for (int o = 16; o > 0; o >>= 1) s += __shfl_xor_sync(0xffffffff, s, o);
    if (lane == 0) wv[gw] = s;
}

__global__ __launch_bounds__(256) void cast_G(
    const float* __restrict__ Gacc, __half* __restrict__ GT)
{
    int i = blockIdx.x * 1024 + threadIdx.x * 4;
    __half2 h0, h1;
    h0.x = __float2half_rn(Gacc[i + 0]);
    h0.y = __float2half_rn(Gacc[i + 1]);
    h1.x = __float2half_rn(Gacc[i + 2]);
    h1.y = __float2half_rn(Gacc[i + 3]);
    uint2 pk;
    pk.x = *(uint32_t*)&h0;
    pk.y = *(uint32_t*)&h1;
    *(uint2*)(GT + i) = pk;
}

// u[i] = xf[i,:].w1 + c0 ; v[i] = xf[i,:].w2   (warp per row)
__global__ __launch_bounds__(256) void uv_kernel(
    const __half* __restrict__ xf, const float* __restrict__ wv,
    float* __restrict__ u, float* __restrict__ v)
{
    __shared__ float w1s[HID], w2s[HID];
    for (int i = threadIdx.x; i < HID; i += 256) {
        w1s[i] = wv[i];
        w2s[i] = wv[HID + i];
    }
    __syncthreads();
    int row = blockIdx.x * 8 + (threadIdx.x >> 5);
    int lane = threadIdx.x & 31;
    float a = 0.f, b = 0.f;
#pragma unroll
    for (int j = 0; j < 16; j++) {
        int idx = j * 32 + lane;
        float xv = __half2float(xf[(size_t)row * HID + idx]);
        a += xv * w1s[idx];
        b += xv * w2s[idx];
    }
#pragma unroll
    for (int o = 16; o > 0; o >>= 1) {
        a += __shfl_xor_sync(0xffffffff, a, o);
        b += __shfl_xor_sync(0xffffffff, b, o);
    }
    if (lane == 0) {
        u[row] = a + wv[2 * HID];
        v[row] = b;
    }
}

// ===========================================================================
// fp16 HMMA GEMM, mbarrier 3-stage pipeline (R13 core).
// CTA 128x128, 128 threads (4 warps, 2x2), warp tile 64x64, K-chunk 64.
// kseg > 0: split-K mode — z selects K-segment of length kseg; epilogue
//           atomicAdd fp32 into Cf.
// Else: Cf: d/rowsum -> fp32 | rowsum: exp epilogue | else: fp16 store.
// ===========================================================================
#define ROW_BYTES   144
#define PLANE_BYTES (128 * ROW_BYTES)     // 18432
#define STAGE_BYTES (2 * PLANE_BYTES)     // 36864
#define NSTAGES     3
#define MBAR_AREA   128
#define GSMEM_TOTAL (MBAR_AREA + NSTAGES * STAGE_BYTES)   // 110720

__global__ __launch_bounds__(128, 2) void gemm_f16(
    const __half* __restrict__ Ap, long long sAb,
    const __half* __restrict__ Bp, long long sBb,
    const float* __restrict__ u, const float* __restrict__ v,
    float scale,
    float* __restrict__ Cf, __half* __restrict__ Ch,
    float* __restrict__ rowsum,
    long long sCb, int N, int K, int kseg)
{
    extern __shared__ __align__(16) char smem[];

    const int tid = threadIdx.x;
    const int wid = tid >> 5;
    const int lid = tid & 31;
    const int warp_m = wid & 1;
    const int warp_n = wid >> 1;
    const int row0 = blockIdx.y * 128;
    const int col0 = blockIdx.x * 128;
    const int z = blockIdx.z;

    const int Keff = kseg ? kseg : K;
    const int kbase = kseg ? z * kseg : 0;
    const __half* srcA = Ap + (kseg ? 0 : (size_t)z * sAb) + (size_t)row0 * K + kbase;
    const __half* srcB = Bp + (kseg ? 0 : (size_t)z * sBb) + (size_t)col0 * K + kbase;

    const uint32_t smb = smem_to_u32(smem);
    const uint32_t tiles = smb + MBAR_AREA;

    if (tid == 0) {
#pragma unroll
        for (int s = 0; s < NSTAGES; s++) {
            MBARRIER_INIT(smb + s * 16, 128);
            MBARRIER_INIT(smb + s * 16 + 8, 4);
        }
    }
    __syncthreads();

    const int ld_r = tid >> 3;
    const int ld_ch = tid & 7;

    const int rA = warp_m * 64 + (lid & 15);
    const uint32_t aoff = (uint32_t)(rA * ROW_BYTES + ((lid >> 4) & 1) * 16);
    const int rB = warp_n * 64 + (lid & 7) + ((lid >> 4) & 1) * 8;
    const uint32_t boff = (uint32_t)(rB * ROW_BYTES + ((lid >> 3) & 1) * 16);

    float d[4][8][4];
#pragma unroll
    for (int i = 0; i < 4; i++)
#pragma unroll
        for (int j = 0; j < 8; j++)
#pragma unroll
            for (int c = 0; c < 4; c++) d[i][j][c] = 0.f;

    const int nchunks = Keff >> 6;

    auto issue = [&](int ci, int st) {
        const int k0 = ci << 6;
        const uint32_t sb = tiles + st * STAGE_BYTES;
#pragma unroll
        for (int t = 0; t < 8; t++) {
            int r = ld_r + t * 16;
            cp_async16(sb + r * ROW_BYTES + ld_ch * 16,
                       srcA + (size_t)r * K + k0 + ld_ch * 8);
        }
#pragma unroll
        for (int t = 0; t < 8; t++) {
            int r = ld_r + t * 16;
            cp_async16(sb + PLANE_BYTES + r * ROW_BYTES + ld_ch * 16,
                       srcB + (size_t)r * K + k0 + ld_ch * 8);
        }
        cp_async_mbar_arrive(smb + st * 16);
    };

    int p_st = 0, p_ph = 1;
    int c_st = 0, c_ph = 0;

#pragma unroll
    for (int s = 0; s < 2; s++) {
        if (s < nchunks) {
            MBARRIER_WAIT_PARITY(smb + p_st * 16 + 8, p_ph);
            issue(s, p_st);
            if (++p_st == NSTAGES) { p_st = 0; p_ph ^= 1; }
        }
    }

    for (int ci = 0; ci < nchunks; ci++) {
        const int nx = ci + 2;
        if (nx < nchunks) {
            MBARRIER_WAIT_PARITY(smb + p_st * 16 + 8, p_ph);
            issue(nx, p_st);
            if (++p_st == NSTAGES) { p_st = 0; p_ph ^= 1; }
        }

        MBARRIER_WAIT_PARITY(smb + c_st * 16, c_ph);

        const uint32_t sb = tiles + c_st * STAGE_BYTES;
        const uint32_t pA = sb;
        const uint32_t pB = sb + PLANE_BYTES;

#pragma unroll
        for (int ks = 0; ks < 4; ks++) {
            const uint32_t kb = ks * 32;
            uint32_t bh[16];
#pragma unroll
            for (int nj = 0; nj < 4; nj++)
                ldsm_x4(bh + nj * 4, pB + boff + kb + nj * 16 * ROW_BYTES);
#pragma unroll
            for (int mi = 0; mi < 4; mi++) {
                uint32_t ah[4];
                ldsm_x4(ah, pA + aoff + kb + mi * 16 * ROW_BYTES);
#pragma unroll
                for (int ni = 0; ni < 8; ni++)
                    mma_f16(d[mi][ni], ah, bh + ni * 2);
            }
        }

        __syncwarp();
        if (lid == 0) MBARRIER_ARRIVE(smb + c_st * 16 + 8);
        if (++c_st == NSTAGES) { c_st = 0; c_ph ^= 1; }
    }

    // ---- epilogue ----
    const int tr = lid >> 2;
    const int tc = (lid & 3) * 2;

    if (kseg) {
        // split-K: atomic accumulate fp32
#pragma unroll
        for (int mi = 0; mi < 4; mi++) {
            int r0g = row0 + warp_m * 64 + mi * 16 + tr;
#pragma unroll
            for (int ni = 0; ni < 8; ni++) {
                int cg = col0 + warp_n * 64 + ni * 8 + tc;
                float* dst0 = Cf + (size_t)r0g * N + cg;
                float* dst1 = dst0 + (size_t)8 * N;
                atomicAdd(dst0 + 0, d[mi][ni][0]);
                atomicAdd(dst0 + 1, d[mi][ni][1]);
                atomicAdd(dst1 + 0, d[mi][ni][2]);
                atomicAdd(dst1 + 1, d[mi][ni][3]);
            }
        }
    } else if (Cf) {
        // out GEMM: normalize by rowsum
#pragma unroll
        for (int mi = 0; mi < 4; mi++) {
            int r0g = row0 + warp_m * 64 + mi * 16 + tr;
            float inv0 = 1.0f / rowsum[z * SEQ + r0g];
            float inv1 = 1.0f / rowsum[z * SEQ + r0g + 8];
#pragma unroll
            for (int ni = 0; ni < 8; ni++) {
                int cg = col0 + warp_n * 64 + ni * 8 + tc;
                float* dst0 = Cf + (size_t)z * sCb + (size_t)r0g * N + cg;
                float* dst1 = dst0 + (size_t)8 * N;
                *(float2*)dst0 = make_float2(d[mi][ni][0] * inv0, d[mi][ni][1] * inv0);
                *(float2*)dst1 = make_float2(d[mi][ni][2] * inv1, d[mi][ni][3] * inv1);
            }
        }
    } else if (rowsum) {
        // scores: e = exp((d + u[i] + v[j])*scale) -> fp16 + rowsum
        float rs[4][2];
#pragma unroll
        for (int mi = 0; mi < 4; mi++) { rs[mi][0] = 0.f; rs[mi][1] = 0.f; }
#pragma unroll
        for (int mi = 0; mi < 4; mi++) {
            int r0g = row0 + warp_m * 64 + mi * 16 + tr;
            float uu0 = u[z * SEQ + r0g];
            float uu1 = u[z * SEQ + r0g + 8];
#pragma unroll
            for (int ni = 0; ni < 8; ni++) {
                int cg = col0 + warp_n * 64 + ni * 8 + tc;
                float vv0 = v[z * SEQ + cg];
                float vv1 = v[z * SEQ + cg + 1];
                float e0 = __expf((d[mi][ni][0] + uu0 + vv0) * scale);
                float e1 = __expf((d[mi][ni][1] + uu0 + vv1) * scale);
                float e2 = __expf((d[mi][ni][2] + uu1 + vv0) * scale);
                float e3 = __expf((d[mi][ni][3] + uu1 + vv1) * scale);
                rs[mi][0] += e0 + e1;
                rs[mi][1] += e2 + e3;
                __half2 p0; p0.x = __float2half_rn(e0); p0.y = __float2half_rn(e1);
                __half2 p1; p1.x = __float2half_rn(e2); p1.y = __float2half_rn(e3);
                size_t o0 = (size_t)z * sCb + (size_t)r0g * N + cg;
                *(__half2*)(Ch + o0) = p0;
                *(__half2*)(Ch + o0 + (size_t)8 * N) = p1;
            }
        }
#pragma unroll
        for (int mi = 0; mi < 4; mi++) {
#pragma unroll
            for (int h = 0; h < 2; h++) {
                float s = rs[mi][h];
                s += __shfl_xor_sync(0xffffffff, s, 1);
                s += __shfl_xor_sync(0xffffffff, s, 2);
                if ((lid & 3) == 0) {
                    int r = row0 + warp_m * 64 + mi * 16 + tr + h * 8;
                    atomicAdd(rowsum + z * SEQ + r, s);
                }
            }
        }
    } else {
        // plain fp16 store (y-GEMM)
#pragma unroll
        for (int mi = 0; mi < 4; mi++) {
            int r0g = row0 + warp_m * 64 + mi * 16 + tr;
#pragma unroll
            for (int ni = 0; ni < 8; ni++) {
                int cg = col0 + warp_n * 64 + ni * 8 + tc;
#pragma unroll
                for (int half = 0; half < 2; half++) {
                    __half2 p;
                    p.x = __float2half_rn(d[mi][ni][half * 2 + 0]);
                    p.y = __float2half_rn(d[mi][ni][half * 2 + 1]);
                    size_t o = (size_t)z * sCb + (size_t)(r0g + half * 8) * N + cg;
                    *(__half2*)(Ch + o) = p;
                }
            }
        }
    }
}

// ---------------------------------------------------------------------------
extern "C" void kernel_launch(void* const* d_in, const int* in_sizes, int n_in,
                              void* d_out, int out_size)
{
    const float* x  = (const float*)d_in[0];  // [8,2048,512]
    const float* Wq = (const float*)d_in[1];  // [512,512]
    const float* bq = (const float*)d_in[2];  // [512]
    const float* Wk = (const float*)d_in[3];  // [512,512]
    const float* bk = (const float*)d_in[4];  // [512]
    float* out = (float*)d_out;               // [8,2048,512]

    cudaFuncSetAttribute(gemm_f16,
                         cudaFuncAttributeMaxDynamicSharedMemorySize, GSMEM_TOTAL);

    __half *xf, *xT, *Wqf, *Wkf, *GT, *yf, *Ef;
    float *rowsum, *wv, *u, *v, *Gacc;
    cudaGetSymbolAddress((void**)&xf,  g_xf);
    cudaGetSymbolAddress((void**)&xT,  g_xT);
    cudaGetSymbolAddress((void**)&Wqf, g_Wqf);
    cudaGetSymbolAddress((void**)&Wkf, g_Wkf);
    cudaGetSymbolAddress((void**)&Gacc, g_Gacc);
    cudaGetSymbolAddress((void**)&GT,  g_GT);
    cudaGetSymbolAddress((void**)&yf,  g_y);
    cudaGetSymbolAddress((void**)&Ef,  g_Ef);
    cudaGetSymbolAddress((void**)&rowsum, g_rowsum);
    cudaGetSymbolAddress((void**)&wv,  g_wvec);
    cudaGetSymbolAddress((void**)&u,   g_u);
    cudaGetSymbolAddress((void**)&v,   g_v);

    const float scaleQ = 1.0f / sqrtf((float)HID);

    // --- weight prep: cast + Gacc zero + wvec ---
    weight_prep<<<385, 256>>>(Wq, Wk, bq, bk, Wqf, Wkf, Gacc, wv);

    // --- GT split-K: Gacc += Wk @ Wq^T  (grid 4x4x4, kseg=128) ---
    {
        dim3 grid(HID / 128, HID / 128, 4);
        gemm_f16<<<grid, 128, GSMEM_TOTAL>>>(
            Wkf, 0, Wqf, 0, nullptr, nullptr, 1.0f,
            Gacc, nullptr, nullptr, 0, HID, HID, 128);
    }
    cast_G<<<HID * HID / 1024, 256>>>(Gacc, GT);

    // --- x prep ---
    {
        dim3 g(HID / 64, SEQ / 64, BATCH);
        fused_prep<<<g, 256>>>(x, xf, xT, rowsum);
    }
    // --- u, v vectors ---
    uv_kernel<<<MROWS / 8, 256>>>(xf, wv, u, v);

    // --- y = xf @ GT^T  (16384x512x512) ---
    {
        dim3 grid(HID / 128, MROWS / 128, 1);
        gemm_f16<<<grid, 128, GSMEM_TOTAL>>>(
            xf, 0, GT, 0, nullptr, nullptr, 1.0f,
            nullptr, yf, nullptr, 0, HID, HID, 0);
    }
    // --- scores+exp: E = exp((y@x^T + u + v)/sqrt(D)) -> fp16 + rowsum ---
    {
        dim3 grid(SEQ / 128, SEQ / 128, BATCH);
        gemm_f16<<<grid, 128, GSMEM_TOTAL>>>(
            yf, (long long)SEQ * HID,
            xf, (long long)SEQ * HID,
            u, v, scaleQ,
            nullptr, Ef, rowsum, (long long)SEQ * SEQ, SEQ, HID, 0);
    }
    // --- out = (E @ xT^T) / rowsum ---
    {
        dim3 grid(HID / 128, SEQ / 128, BATCH);
        gemm_f16<<<grid, 128, GSMEM_TOTAL>>>(
            Ef, (long long)SEQ * SEQ,
            xT, (long long)HID * SEQ,
            nullptr, nullptr, 1.0f,
            out, nullptr, rowsum, (long long)SEQ * HID, HID, SEQ, 0);
    }
}

// round 17
// speedup vs baseline: 3.4396x; 1.0190x over previous
#include <cuda_runtime.h>
#include <cuda_fp16.h>
#include <cstdint>
#include <math.h>

// ===========================================================================
// SelfAttention, fp16 HMMA pipeline (base sm_103 ISA).
// R16: R15 kernels unchanged; kernel_launch uses a capture-forked second
// stream so the weight chain (weight_prep -> GT splitK -> cast_G) overlaps
// fused_prep, and uv overlaps the y-GEMM.
//   stream0: fused_prep -> [GT ready] y -> [uv ready] scores -> out
//   stream2: weight_prep -> GT -> cast_G -> [xf ready] uv
// ===========================================================================

#define BATCH 8
#define SEQ   2048
#define HID   512
#define MROWS (BATCH * SEQ)   // 16384

// ---------------- scratch (__device__ globals) ----------------
__device__ __half g_xf [MROWS * HID];
__device__ __half g_xT [MROWS * HID];          // per-batch [512,2048]
__device__ __half g_Wqf[HID * HID];
__device__ __half g_Wkf[HID * HID];
__device__ float  g_Gacc[HID * HID];           // fp32 split-K accumulator
__device__ __half g_GT [HID * HID];            // GT[c,d] = G[d,c]
__device__ __half g_y  [MROWS * HID];          // y = x @ G
__device__ __half g_Ef [(size_t)BATCH * SEQ * SEQ]; // 67 MB exp(S)
__device__ float  g_rowsum[MROWS];
__device__ float  g_wvec[2 * HID + 32];        // w1 | w2 | c0 at [1024]
__device__ float  g_u[MROWS];
__device__ float  g_v[MROWS];

// ---------------- asm helpers (base ISA) ----------------
__device__ __forceinline__ void ldsm_x4(uint32_t* r, uint32_t addr) {
    asm volatile("ldmatrix.sync.aligned.m8n8.x4.shared.b16 {%0,%1,%2,%3}, [%4];"
                 : "=r"(r[0]), "=r"(r[1]), "=r"(r[2]), "=r"(r[3]) : "r"(addr));
}
__device__ __forceinline__ void mma_f16(float* d, const uint32_t* a, const uint32_t* b) {
    asm volatile(
        "mma.sync.aligned.m16n8k16.row.col.f32.f16.f16.f32 "
        "{%0,%1,%2,%3}, {%4,%5,%6,%7}, {%8,%9}, {%0,%1,%2,%3};"
        : "+f"(d[0]), "+f"(d[1]), "+f"(d[2]), "+f"(d[3])
        : "r"(a[0]), "r"(a[1]), "r"(a[2]), "r"(a[3]), "r"(b[0]), "r"(b[1]));
}
__device__ __forceinline__ uint32_t smem_to_u32(const void* p) {
    uint32_t a;
    asm("{ .reg .u64 t; cvta.to.shared.u64 t, %1; cvt.u32.u64 %0, t; }"
        : "=r"(a) : "l"(p));
    return a;
}
__device__ __forceinline__ void cp_async16(uint32_t dst, const void* src) {
    asm volatile("cp.async.cg.shared.global [%0], [%1], 16;"
                 :: "r"(dst), "l"(src));
}
__device__ __forceinline__ void cp_async_mbar_arrive(uint32_t mbar) {
    asm volatile("cp.async.mbarrier.arrive.noinc.shared::cta.b64 [%0];"
                 :: "r"(mbar) : "memory");
}
#define MBARRIER_INIT(mbar, cnt) \
    asm volatile("mbarrier.init.shared.b64 [%0], %1;" \
                 :: "r"((uint32_t)(mbar)), "r"((uint32_t)(cnt)) : "memory")
#define MBARRIER_ARRIVE(mbar) \
    asm volatile("mbarrier.arrive.shared.b64 _, [%0];" \
                 :: "r"((uint32_t)(mbar)) : "memory")
#define MBARRIER_WAIT_PARITY(mbar, parity) do {                              \
    uint32_t _m = (uint32_t)(mbar); uint32_t _p = (uint32_t)(parity);        \
    uint32_t _done;                                                          \
    asm volatile(                                                            \
        "{\n\t.reg .pred p;\n\t"                                             \
        "mbarrier.try_wait.parity.acquire.cta.shared::cta.b64 p, [%1], %2;\n\t" \
        "selp.b32 %0, 1, 0, p;\n\t}"                                         \
        : "=r"(_done) : "r"(_m), "r"(_p) : "memory");                        \
    if (!_done) {                                                            \
        asm volatile(                                                        \
            "{\n\t.reg .pred P1;\n\t"                                        \
            "WAIT_LOOP_%=:\n\t"                                              \
            "mbarrier.try_wait.parity.acquire.cta.shared::cta.b64 P1, [%0], %1, 0x989680;\n\t" \
            "@P1 bra.uni WAIT_DONE_%=;\n\t"                                  \
            "bra.uni WAIT_LOOP_%=;\n\t"                                      \
            "WAIT_DONE_%=:\n\t}"                                             \
            :: "r"(_m), "r"(_p) : "memory");                                 \
    }                                                                        \
} while (0)

// ---------------- prep: vectorized split + transpose ----------------
__global__ __launch_bounds__(256) void fused_prep(
    const float* __restrict__ x, __half* __restrict__ xf,
    __half* __restrict__ xT, float* __restrict__ rowsum)
{
    __shared__ float t[64][65];
    const size_t base = (size_t)blockIdx.z * SEQ * HID;
    const int c0 = blockIdx.x * 64;   // hid
    const int r0 = blockIdx.y * 64;   // seq
    const int tid = threadIdx.x;

#pragma unroll
    for (int p = 0; p < 4; p++) {
        int idx = tid + p * 256;          // 0..1023
        int r = idx >> 4;                 // 0..63
        int c4 = idx & 15;                // float4 index
        float4 v = *(const float4*)(x + base + (size_t)(r0 + r) * HID + c0 + c4 * 4);
        t[r][c4 * 4 + 0] = v.x;
        t[r][c4 * 4 + 1] = v.y;
        t[r][c4 * 4 + 2] = v.z;
        t[r][c4 * 4 + 3] = v.w;
        __half2 h0, h1;
        h0.x = __float2half_rn(v.x); h0.y = __float2half_rn(v.y);
        h1.x = __float2half_rn(v.z); h1.y = __float2half_rn(v.w);
        uint2 pk;
        pk.x = *(uint32_t*)&h0;
        pk.y = *(uint32_t*)&h1;
        *(uint2*)(xf + base + (size_t)(r0 + r) * HID + c0 + c4 * 4) = pk;
    }
    if (blockIdx.x == 0 && blockIdx.z == 0) {
        rowsum[blockIdx.y * 512 + tid] = 0.f;
        rowsum[blockIdx.y * 512 + 256 + tid] = 0.f;
    }
    __syncthreads();
#pragma unroll
    for (int p = 0; p < 4; p++) {
        int idx = tid + p * 256;
        int c = idx >> 4;                 // hid within tile
        int r4 = idx & 15;                // seq quad
        float v0 = t[r4 * 4 + 0][c];
        float v1 = t[r4 * 4 + 1][c];
        float v2 = t[r4 * 4 + 2][c];
        float v3 = t[r4 * 4 + 3][c];
        __half2 h0, h1;
        h0.x = __float2half_rn(v0); h0.y = __float2half_rn(v1);
        h1.x = __float2half_rn(v2); h1.y = __float2half_rn(v3);
        uint2 pk;
        pk.x = *(uint32_t*)&h0;
        pk.y = *(uint32_t*)&h1;
        *(uint2*)(xT + base + (size_t)(c0 + c) * SEQ + r0 + r4 * 4) = pk;
    }
}

// ---------------- merged weight prep ----------------
__global__ __launch_bounds__(256) void weight_prep(
    const float* __restrict__ Wq, const float* __restrict__ Wk,
    const float* __restrict__ bq, const float* __restrict__ bk,
    __half* __restrict__ Wqf, __half* __restrict__ Wkf,
    float* __restrict__ Gacc, float* __restrict__ wv)
{
    const int b = blockIdx.x;
    if (b < 256) {
        int i0 = b * 1024 + threadIdx.x * 4;
#pragma unroll
        for (int k = 0; k < 4; k++) {
            int i = i0 + k;
            Wqf[i] = __float2half_rn(Wq[i]);
            Wkf[i] = __float2half_rn(Wk[i]);
            Gacc[i] = 0.f;
        }
        return;
    }
    int gw = (b - 256) * 8 + (threadIdx.x >> 5);
    int lane = threadIdx.x & 31;
    float s = 0.f;
    if (gw < HID) {
#pragma unroll
        for (int j = 0; j < 16; j++) {
            int idx = j * 32 + lane;
            s += Wq[(size_t)gw * HID + idx] * bk[idx];
        }
    } else if (gw < 2 * HID) {
        int d = gw - HID;
#pragma unroll
        for (int j = 0; j < 16; j++) {
            int idx = j * 32 + lane;
            s += Wk[(size_t)d * HID + idx] * bq[idx];
        }
    } else if (gw == 2 * HID) {
#pragma unroll
        for (int j = 0; j < 16; j++) {
            int idx = j * 32 + lane;
            s += bq[idx] * bk[idx];
        }
    } else {
        return;
    }
#pragma unroll
    for (int o = 16; o > 0; o >>= 1) s += __shfl_xor_sync(0xffffffff, s, o);
    if (lane == 0) wv[gw] = s;
}

__global__ __launch_bounds__(256) void cast_G(
    const float* __restrict__ Gacc, __half* __restrict__ GT)
{
    int i = blockIdx.x * 1024 + threadIdx.x * 4;
    __half2 h0, h1;
    h0.x = __float2half_rn(Gacc[i + 0]);
    h0.y = __float2half_rn(Gacc[i + 1]);
    h1.x = __float2half_rn(Gacc[i + 2]);
    h1.y = __float2half_rn(Gacc[i + 3]);
    uint2 pk;
    pk.x = *(uint32_t*)&h0;
    pk.y = *(uint32_t*)&h1;
    *(uint2*)(GT + i) = pk;
}

// u[i] = xf[i,:].w1 + c0 ; v[i] = xf[i,:].w2   (warp per row)
__global__ __launch_bounds__(256) void uv_kernel(
    const __half* __restrict__ xf, const float* __restrict__ wv,
    float* __restrict__ u, float* __restrict__ v)
{
    __shared__ float w1s[HID], w2s[HID];
    for (int i = threadIdx.x; i < HID; i += 256) {
        w1s[i] = wv[i];
        w2s[i] = wv[HID + i];
    }
    __syncthreads();
    int row = blockIdx.x * 8 + (threadIdx.x >> 5);
    int lane = threadIdx.x & 31;
    float a = 0.f, b = 0.f;
#pragma unroll
    for (int j = 0; j < 16; j++) {
        int idx = j * 32 + lane;
        float xv = __half2float(xf[(size_t)row * HID + idx]);
        a += xv * w1s[idx];
        b += xv * w2s[idx];
    }
#pragma unroll
    for (int o = 16; o > 0; o >>= 1) {
        a += __shfl_xor_sync(0xffffffff, a, o);
        b += __shfl_xor_sync(0xffffffff, b, o);
    }
    if (lane == 0) {
        u[row] = a + wv[2 * HID];
        v[row] = b;
    }
}

// ===========================================================================
// fp16 HMMA GEMM, mbarrier 3-stage pipeline (R13 core).
// ===========================================================================
#define ROW_BYTES   144
#define PLANE_BYTES (128 * ROW_BYTES)     // 18432
#define STAGE_BYTES (2 * PLANE_BYTES)     // 36864
#define NSTAGES     3
#define MBAR_AREA   128
#define GSMEM_TOTAL (MBAR_AREA + NSTAGES * STAGE_BYTES)   // 110720

__global__ __launch_bounds__(128, 2) void gemm_f16(
    const __half* __restrict__ Ap, long long sAb,
    const __half* __restrict__ Bp, long long sBb,
    const float* __restrict__ u, const float* __restrict__ v,
    float scale,
    float* __restrict__ Cf, __half* __restrict__ Ch,
    float* __restrict__ rowsum,
    long long sCb, int N, int K, int kseg)
{
    extern __shared__ __align__(16) char smem[];

    const int tid = threadIdx.x;
    const int wid = tid >> 5;
    const int lid = tid & 31;
    const int warp_m = wid & 1;
    const int warp_n = wid >> 1;
    const int row0 = blockIdx.y * 128;
    const int col0 = blockIdx.x * 128;
    const int z = blockIdx.z;

    const int Keff = kseg ? kseg : K;
    const int kbase = kseg ? z * kseg : 0;
    const __half* srcA = Ap + (kseg ? 0 : (size_t)z * sAb) + (size_t)row0 * K + kbase;
    const __half* srcB = Bp + (kseg ? 0 : (size_t)z * sBb) + (size_t)col0 * K + kbase;

    const uint32_t smb = smem_to_u32(smem);
    const uint32_t tiles = smb + MBAR_AREA;

    if (tid == 0) {
#pragma unroll
        for (int s = 0; s < NSTAGES; s++) {
            MBARRIER_INIT(smb + s * 16, 128);
            MBARRIER_INIT(smb + s * 16 + 8, 4);
        }
    }
    __syncthreads();

    const int ld_r = tid >> 3;
    const int ld_ch = tid & 7;

    const int rA = warp_m * 64 + (lid & 15);
    const uint32_t aoff = (uint32_t)(rA * ROW_BYTES + ((lid >> 4) & 1) * 16);
    const int rB = warp_n * 64 + (lid & 7) + ((lid >> 4) & 1) * 8;
    const uint32_t boff = (uint32_t)(rB * ROW_BYTES + ((lid >> 3) & 1) * 16);

    float d[4][8][4];
#pragma unroll
    for (int i = 0; i < 4; i++)
#pragma unroll
        for (int j = 0; j < 8; j++)
#pragma unroll
            for (int c = 0; c < 4; c++) d[i][j][c] = 0.f;

    const int nchunks = Keff >> 6;

    auto issue = [&](int ci, int st) {
        const int k0 = ci << 6;
        const uint32_t sb = tiles + st * STAGE_BYTES;
#pragma unroll
        for (int t = 0; t < 8; t++) {
            int r = ld_r + t * 16;
            cp_async16(sb + r * ROW_BYTES + ld_ch * 16,
                       srcA + (size_t)r * K + k0 + ld_ch * 8);
        }
#pragma unroll
        for (int t = 0; t < 8; t++) {
            int r = ld_r + t * 16;
            cp_async16(sb + PLANE_BYTES + r * ROW_BYTES + ld_ch * 16,
                       srcB + (size_t)r * K + k0 + ld_ch * 8);
        }
        cp_async_mbar_arrive(smb + st * 16);
    };

    int p_st = 0, p_ph = 1;
    int c_st = 0, c_ph = 0;

#pragma unroll
    for (int s = 0; s < 2; s++) {
        if (s < nchunks) {
            MBARRIER_WAIT_PARITY(smb + p_st * 16 + 8, p_ph);
            issue(s, p_st);
            if (++p_st == NSTAGES) { p_st = 0; p_ph ^= 1; }
        }
    }

    for (int ci = 0; ci < nchunks; ci++) {
        const int nx = ci + 2;
        if (nx < nchunks) {
            MBARRIER_WAIT_PARITY(smb + p_st * 16 + 8, p_ph);
            issue(nx, p_st);
            if (++p_st == NSTAGES) { p_st = 0; p_ph ^= 1; }
        }

        MBARRIER_WAIT_PARITY(smb + c_st * 16, c_ph);

        const uint32_t sb = tiles + c_st * STAGE_BYTES;
        const uint32_t pA = sb;
        const uint32_t pB = sb + PLANE_BYTES;

#pragma unroll
        for (int ks = 0; ks < 4; ks++) {
            const uint32_t kb = ks * 32;
            uint32_t bh[16];
#pragma unroll
            for (int nj = 0; nj < 4; nj++)
                ldsm_x4(bh + nj * 4, pB + boff + kb + nj * 16 * ROW_BYTES);
#pragma unroll
            for (int mi = 0; mi < 4; mi++) {
                uint32_t ah[4];
                ldsm_x4(ah, pA + aoff + kb + mi * 16 * ROW_BYTES);
#pragma unroll
                for (int ni = 0; ni < 8; ni++)
                    mma_f16(d[mi][ni], ah, bh + ni * 2);
            }
        }

        __syncwarp();
        if (lid == 0) MBARRIER_ARRIVE(smb + c_st * 16 + 8);
        if (++c_st == NSTAGES) { c_st = 0; c_ph ^= 1; }
    }

    // ---- epilogue ----
    const int tr = lid >> 2;
    const int tc = (lid & 3) * 2;

    if (kseg) {
#pragma unroll
        for (int mi = 0; mi < 4; mi++) {
            int r0g = row0 + warp_m * 64 + mi * 16 + tr;
#pragma unroll
            for (int ni = 0; ni < 8; ni++) {
                int cg = col0 + warp_n * 64 + ni * 8 + tc;
                float* dst0 = Cf + (size_t)r0g * N + cg;
                float* dst1 = dst0 + (size_t)8 * N;
                atomicAdd(dst0 + 0, d[mi][ni][0]);
                atomicAdd(dst0 + 1, d[mi][ni][1]);
                atomicAdd(dst1 + 0, d[mi][ni][2]);
                atomicAdd(dst1 + 1, d[mi][ni][3]);
            }
        }
    } else if (Cf) {
#pragma unroll
        for (int mi = 0; mi < 4; mi++) {
            int r0g = row0 + warp_m * 64 + mi * 16 + tr;
            float inv0 = 1.0f / rowsum[z * SEQ + r0g];
            float inv1 = 1.0f / rowsum[z * SEQ + r0g + 8];
#pragma unroll
            for (int ni = 0; ni < 8; ni++) {
                int cg = col0 + warp_n * 64 + ni * 8 + tc;
                float* dst0 = Cf + (size_t)z * sCb + (size_t)r0g * N + cg;
                float* dst1 = dst0 + (size_t)8 * N;
                *(float2*)dst0 = make_float2(d[mi][ni][0] * inv0, d[mi][ni][1] * inv0);
                *(float2*)dst1 = make_float2(d[mi][ni][2] * inv1, d[mi][ni][3] * inv1);
            }
        }
    } else if (rowsum) {
        float rs[4][2];
#pragma unroll
        for (int mi = 0; mi < 4; mi++) { rs[mi][0] = 0.f; rs[mi][1] = 0.f; }
#pragma unroll
        for (int mi = 0; mi < 4; mi++) {
            int r0g = row0 + warp_m * 64 + mi * 16 + tr;
            float uu0 = u[z * SEQ + r0g];
            float uu1 = u[z * SEQ + r0g + 8];
#pragma unroll
            for (int ni = 0; ni < 8; ni++) {
                int cg = col0 + warp_n * 64 + ni * 8 + tc;
                float vv0 = v[z * SEQ + cg];
                float vv1 = v[z * SEQ + cg + 1];
                float e0 = __expf((d[mi][ni][0] + uu0 + vv0) * scale);
                float e1 = __expf((d[mi][ni][1] + uu0 + vv1) * scale);
                float e2 = __expf((d[mi][ni][2] + uu1 + vv0) * scale);
                float e3 = __expf((d[mi][ni][3] + uu1 + vv1) * scale);
                rs[mi][0] += e0 + e1;
                rs[mi][1] += e2 + e3;
                __half2 p0; p0.x = __float2half_rn(e0); p0.y = __float2half_rn(e1);
                __half2 p1; p1.x = __float2half_rn(e2); p1.y = __float2half_rn(e3);
                size_t o0 = (size_t)z * sCb + (size_t)r0g * N + cg;
                *(__half2*)(Ch + o0) = p0;
                *(__half2*)(Ch + o0 + (size_t)8 * N) = p1;
            }
        }
#pragma unroll
        for (int mi = 0; mi < 4; mi++) {
#pragma unroll
            for (int h = 0; h < 2; h++) {
                float s = rs[mi][h];
                s += __shfl_xor_sync(0xffffffff, s, 1);
                s += __shfl_xor_sync(0xffffffff, s, 2);
                if ((lid & 3) == 0) {
                    int r = row0 + warp_m * 64 + mi * 16 + tr + h * 8;
                    atomicAdd(rowsum + z * SEQ + r, s);
                }
            }
        }
    } else {
#pragma unroll
        for (int mi = 0; mi < 4; mi++) {
            int r0g = row0 + warp_m * 64 + mi * 16 + tr;
#pragma unroll
            for (int ni = 0; ni < 8; ni++) {
                int cg = col0 + warp_n * 64 + ni * 8 + tc;
#pragma unroll
                for (int half = 0; half < 2; half++) {
                    __half2 p;
                    p.x = __float2half_rn(d[mi][ni][half * 2 + 0]);
                    p.y = __float2half_rn(d[mi][ni][half * 2 + 1]);
                    size_t o = (size_t)z * sCb + (size_t)(r0g + half * 8) * N + cg;
                    *(__half2*)(Ch + o) = p;
                }
            }
        }
    }
}

// ---------------------------------------------------------------------------
extern "C" void kernel_launch(void* const* d_in, const int* in_sizes, int n_in,
                              void* d_out, int out_size)
{
    const float* x  = (const float*)d_in[0];  // [8,2048,512]
    const float* Wq = (const float*)d_in[1];  // [512,512]
    const float* bq = (const float*)d_in[2];  // [512]
    const float* Wk = (const float*)d_in[3];  // [512,512]
    const float* bk = (const float*)d_in[4];  // [512]
    float* out = (float*)d_out;               // [8,2048,512]

    cudaFuncSetAttribute(gemm_f16,
                         cudaFuncAttributeMaxDynamicSharedMemorySize, GSMEM_TOTAL);

    // side stream + fork/join events (created once, on the uncaptured
    // correctness call; per-call work is identical thereafter)
    static cudaStream_t s2 = nullptr;
    static cudaEvent_t evFork = nullptr, evG = nullptr, evXf = nullptr, evUV = nullptr;
    if (!s2) {
        cudaStreamCreateWithFlags(&s2, cudaStreamNonBlocking);
        cudaEventCreateWithFlags(&evFork, cudaEventDisableTiming);
        cudaEventCreateWithFlags(&evG,    cudaEventDisableTiming);
        cudaEventCreateWithFlags(&evXf,   cudaEventDisableTiming);
        cudaEventCreateWithFlags(&evUV,   cudaEventDisableTiming);
    }

    __half *xf, *xT, *Wqf, *Wkf, *GT, *yf, *Ef;
    float *rowsum, *wv, *u, *v, *Gacc;
    cudaGetSymbolAddress((void**)&xf,  g_xf);
    cudaGetSymbolAddress((void**)&xT,  g_xT);
    cudaGetSymbolAddress((void**)&Wqf, g_Wqf);
    cudaGetSymbolAddress((void**)&Wkf, g_Wkf);
    cudaGetSymbolAddress((void**)&Gacc, g_Gacc);
    cudaGetSymbolAddress((void**)&GT,  g_GT);
    cudaGetSymbolAddress((void**)&yf,  g_y);
    cudaGetSymbolAddress((void**)&Ef,  g_Ef);
    cudaGetSymbolAddress((void**)&rowsum, g_rowsum);
    cudaGetSymbolAddress((void**)&wv,  g_wvec);
    cudaGetSymbolAddress((void**)&u,   g_u);
    cudaGetSymbolAddress((void**)&v,   g_v);

    const float scaleQ = 1.0f / sqrtf((float)HID);

    // ---- fork side stream ----
    cudaEventRecord(evFork, 0);
    cudaStreamWaitEvent(s2, evFork, 0);

    // side stream: weight chain
    weight_prep<<<385, 256, 0, s2>>>(Wq, Wk, bq, bk, Wqf, Wkf, Gacc, wv);
    {
        dim3 grid(HID / 128, HID / 128, 4);
        gemm_f16<<<grid, 128, GSMEM_TOTAL, s2>>>(
            Wkf, 0, Wqf, 0, nullptr, nullptr, 1.0f,
            Gacc, nullptr, nullptr, 0, HID, HID, 128);
    }
    cast_G<<<HID * HID / 1024, 256, 0, s2>>>(Gacc, GT);
    cudaEventRecord(evG, s2);

    // main stream: x prep
    {
        dim3 g(HID / 64, SEQ / 64, BATCH);
        fused_prep<<<g, 256>>>(x, xf, xT, rowsum);
    }
    cudaEventRecord(evXf, 0);

    // side stream: uv (needs xf + wv)
    cudaStreamWaitEvent(s2, evXf, 0);
    uv_kernel<<<MROWS / 8, 256, 0, s2>>>(xf, wv, u, v);
    cudaEventRecord(evUV, s2);

    // main stream: y = xf @ GT^T  (needs GT)
    cudaStreamWaitEvent(0, evG, 0);
    {
        dim3 grid(HID / 128, MROWS / 128, 1);
        gemm_f16<<<grid, 128, GSMEM_TOTAL>>>(
            xf, 0, GT, 0, nullptr, nullptr, 1.0f,
            nullptr, yf, nullptr, 0, HID, HID, 0);
    }
    // scores needs u,v from side stream
    cudaStreamWaitEvent(0, evUV, 0);
    {
        dim3 grid(SEQ / 128, SEQ / 128, BATCH);
        gemm_f16<<<grid, 128, GSMEM_TOTAL>>>(
            yf, (long long)SEQ * HID,
            xf, (long long)SEQ * HID,
            u, v, scaleQ,
            nullptr, Ef, rowsum, (long long)SEQ * SEQ, SEQ, HID, 0);
    }
    // out = (E @ xT^T) / rowsum
    {
        dim3 grid(HID / 128, SEQ / 128, BATCH);
        gemm_f16<<<grid, 128, GSMEM_TOTAL>>>(
            Ef, (long long)SEQ * SEQ,
            xT, (long long)HID * SEQ,
            nullptr, nullptr, 1.0f,
            out, nullptr, rowsum, (long long)SEQ * HID, HID, SEQ, 0);
    }
}